// round 4
// baseline (speedup 1.0000x reference)
#include <cuda_runtime.h>
#include <cuda_bf16.h>
#include <math.h>
#include <stdint.h>

// Problem shapes
#define Bn  256
#define Kn  64
#define Dn  1024
#define Hn  4
#define NLn 3

// Output layout in d_out (fp32): logits (B*NL), alpha (B*H*K), head_weights (B*H)
#define ALPHA_OFF 768
#define HW_OFF    (768 + Bn*Hn*Kn)

// HMMA GEMM tiling
#define TCM 128                 // rows per CTA tile
#define TCN 256                 // e-cols per CTA tile
#define KC  64                  // K elems per chunk (64 bf16 = 128B row)
#define NCHUNK (Dn / KC)        // 16
#define NET    (Dn / TCN)       // 4 e-tiles
#define NTHREADS 512

typedef unsigned long long u64;

// -------- scratch (static device globals; no allocation allowed) --------
__device__ float g_wcsum[Hn * Dn];
__device__ float g_upart[NET * Bn * Hn * Kn];   // 1 MB
__device__ float g_eah[Bn * Hn * Dn];
__device__ float g_hw[Bn * Hn];
__device__ float g_feat[Bn * 4 * Dn];
__device__ float g_hidpart[4 * Bn * Dn];
// bf16 split operands
__device__ __nv_bfloat16 g_Ehi[Bn * Kn * Dn];   // 32 MB
__device__ __nv_bfloat16 g_Elo[Bn * Kn * Dn];   // 32 MB
__device__ __nv_bfloat16 g_Wthi[Hn * Dn * Dn];  // 8 MB  (transposed: [h][e][d])
__device__ __nv_bfloat16 g_Wtlo[Hn * Dn * Dn];  // 8 MB

// -------- helpers --------
__device__ __forceinline__ uint32_t smem_u32(const void* p) {
    uint32_t a;
    asm("{ .reg .u64 t; cvta.to.shared.u64 t, %1; cvt.u32.u64 %0, t; }" : "=r"(a) : "l"(p));
    return a;
}
__device__ __forceinline__ float tanhfast(float x) {
    float y; asm("tanh.approx.f32 %0, %1;" : "=f"(y) : "f"(x)); return y;
}
#define SWZ128(o) ((o) ^ (((o) >> 3) & 0x70))

__device__ __forceinline__ void cp16(uint32_t saddr, const void* gptr) {
    asm volatile("cp.async.cg.shared.global [%0], [%1], 16;"
                 :: "r"(saddr), "l"(__cvta_generic_to_global(gptr)) : "memory");
}
#define CP_COMMIT() asm volatile("cp.async.commit_group;" ::: "memory")
#define CP_WAIT(n)  asm volatile("cp.async.wait_group %0;" :: "n"(n) : "memory")

#define LDSM_X4(r0, r1, r2, r3, addr) \
    asm volatile("ldmatrix.sync.aligned.m8n8.x4.shared.b16 {%0,%1,%2,%3}, [%4];" \
                 : "=r"(r0), "=r"(r1), "=r"(r2), "=r"(r3) : "r"(addr))

#define MMA_BF16(c, a, b) \
    asm volatile("mma.sync.aligned.m16n8k16.row.col.f32.bf16.bf16.f32 " \
                 "{%0,%1,%2,%3}, {%4,%5,%6,%7}, {%8,%9}, {%0,%1,%2,%3};" \
                 : "+f"((c)[0]), "+f"((c)[1]), "+f"((c)[2]), "+f"((c)[3]) \
                 : "r"((a)[0]), "r"((a)[1]), "r"((a)[2]), "r"((a)[3]), \
                   "r"((b)[0]), "r"((b)[1]))

// smem stage layout (per stage: Ahi, Alo = 128x128B each; Bhi, Blo = 256x128B each)
#define OFF_AHI 0
#define OFF_ALO 16384
#define OFF_BHI 32768
#define OFF_BLO 65536
#define STAGE_BYTES 98304
#define SM_EXTRA (2 * STAGE_BYTES)                    // epilogue arrays beyond stages
#define SMEM_TOTAL (2 * STAGE_BYTES + 7168)           // 203776

// -------- K0a: split e_emb into bf16 hi/lo --------
__global__ void k_cvtE(const float* __restrict__ e) {
    size_t i = (size_t)blockIdx.x * 256 + threadIdx.x;   // over float4s
    float4 x = ((const float4*)e)[i];
    __nv_bfloat16 h0 = __float2bfloat16(x.x), h1 = __float2bfloat16(x.y);
    __nv_bfloat16 h2 = __float2bfloat16(x.z), h3 = __float2bfloat16(x.w);
    __nv_bfloat16 l0 = __float2bfloat16(x.x - __bfloat162float(h0));
    __nv_bfloat16 l1 = __float2bfloat16(x.y - __bfloat162float(h1));
    __nv_bfloat16 l2 = __float2bfloat16(x.z - __bfloat162float(h2));
    __nv_bfloat16 l3 = __float2bfloat16(x.w - __bfloat162float(h3));
    ((__nv_bfloat162*)g_Ehi)[2*i    ] = __halves2bfloat162(h0, h1);
    ((__nv_bfloat162*)g_Ehi)[2*i + 1] = __halves2bfloat162(h2, h3);
    ((__nv_bfloat162*)g_Elo)[2*i    ] = __halves2bfloat162(l0, l1);
    ((__nv_bfloat162*)g_Elo)[2*i + 1] = __halves2bfloat162(l2, l3);
}

// -------- K0b: transpose W_e[h][d][e] -> Wt[h][e][d], split hi/lo --------
__global__ void k_cvtW(const float* __restrict__ W) {
    __shared__ float t[32][33];
    const int h  = blockIdx.z;
    const int dB = blockIdx.y * 32;
    const int eB = blockIdx.x * 32;
    const int lx = threadIdx.x & 31, ly = threadIdx.x >> 5;  // 32 x 8
    #pragma unroll
    for (int r = 0; r < 4; ++r)
        t[ly + 8*r][lx] = W[((size_t)h*Dn + dB + ly + 8*r) * Dn + eB + lx];
    __syncthreads();
    #pragma unroll
    for (int r = 0; r < 4; ++r) {
        float x = t[lx][ly + 8*r];
        __nv_bfloat16 hi = __float2bfloat16(x);
        __nv_bfloat16 lo = __float2bfloat16(x - __bfloat162float(hi));
        size_t oi = ((size_t)h*Dn + eB + ly + 8*r) * Dn + dB + lx;
        g_Wthi[oi] = hi;
        g_Wtlo[oi] = lo;
    }
}

// -------- K1: Wc_sum[h,d] = sum_e W_c[h,d,e] --------
__global__ void k_wcsum(const float* __restrict__ W_c) {
    int warp = (blockIdx.x * blockDim.x + threadIdx.x) >> 5;
    int lane = threadIdx.x & 31;
    if (warp >= Hn * Dn) return;
    const float* p = W_c + (size_t)warp * Dn;
    float s = 0.f;
    #pragma unroll 8
    for (int j = lane; j < Dn; j += 32) s += p[j];
    #pragma unroll
    for (int o = 16; o; o >>= 1) s += __shfl_down_sync(0xffffffffu, s, o);
    if (!lane) g_wcsum[warp] = s;
}

// -------- K2: HMMA fused  P = E @ Wt^T (3-term bf16 split);
//              u_part = sum_e tanh(cp + P) * v  over this CTA's 256 e-cols ----
__global__ void __launch_bounds__(NTHREADS, 1)
k_attn_mma(const float* __restrict__ c_out, const float* __restrict__ v)
{
    extern __shared__ char smem[];
    const uint32_t sb = smem_u32(smem);
    const int tid   = threadIdx.x;
    const int wid   = tid >> 5;
    const int lane  = tid & 31;
    const int warpM = wid >> 3;     // 0..1
    const int warpN = wid & 7;      // 0..7

    const int et      = blockIdx.x;          // 0..3
    const int rowBase = blockIdx.y * TCM;    // global GEMM row base
    const int h       = blockIdx.z;          // 0..3
    const int eBase   = et * TCN;

    const __nv_bfloat16* Ahi = g_Ehi  + (size_t)rowBase * Dn;
    const __nv_bfloat16* Alo = g_Elo  + (size_t)rowBase * Dn;
    const __nv_bfloat16* Bhi = g_Wthi + ((size_t)h * Dn + eBase) * Dn;
    const __nv_bfloat16* Blo = g_Wtlo + ((size_t)h * Dn + eBase) * Dn;

    // epilogue smem region (beyond the two stages)
    float* s_cce0 = (float*)(smem + SM_EXTRA);       // 256
    float* s_cce1 = s_cce0 + TCN;                    // 256
    float* s_vv   = s_cce1 + TCN;                    // 256
    float* s_red  = s_vv + TCN;                      // [128][8]

    const int b0 = rowBase >> 6;
    {   // precompute per-column scalars (overlaps with first loads)
        int e = eBase + (tid & 255);
        float wc = g_wcsum[h * Dn + e];
        if (tid < 256) {
            s_cce0[tid] = c_out[b0 * Dn + e] * wc;
            s_vv[tid]   = v[h * Dn + e];
        } else {
            s_cce1[tid - 256] = c_out[(b0 + 1) * Dn + e] * wc;
        }
    }

    // per-thread load mapping: A = 1024 16B segs (x2 for hi/lo), B = 2048 segs
    int arow[2], ac16[2]; uint32_t aso[2];
    #pragma unroll
    for (int i = 0; i < 2; ++i) {
        int seg = tid + i * NTHREADS;
        arow[i] = seg >> 3; ac16[i] = seg & 7;
        aso[i] = SWZ128((uint32_t)(arow[i] * 128 + ac16[i] * 16));
    }
    int brow[4], bc16[4]; uint32_t bso[4];
    #pragma unroll
    for (int i = 0; i < 4; ++i) {
        int seg = tid + i * NTHREADS;
        brow[i] = seg >> 3; bc16[i] = seg & 7;
        bso[i] = SWZ128((uint32_t)(brow[i] * 128 + bc16[i] * 16));
    }

    float acc[4][4][4];
    #pragma unroll
    for (int mt = 0; mt < 4; ++mt)
        #pragma unroll
        for (int nt = 0; nt < 4; ++nt)
            #pragma unroll
            for (int j = 0; j < 4; ++j) acc[mt][nt][j] = 0.f;

    // ldmatrix base offsets
    const uint32_t aRowB = (uint32_t)((warpM * 64 + (lane & 15)) * 128);
    const uint32_t bRowB = (uint32_t)((warpN * 32 + (lane & 15)) * 128);
    const uint32_t colSel = (uint32_t)((lane >> 4) * 16);

    // prologue: issue chunk 0
    {
        const uint32_t st = sb;
        #pragma unroll
        for (int i = 0; i < 2; ++i) {
            size_t g = (size_t)arow[i] * Dn + ac16[i] * 8;
            cp16(st + OFF_AHI + aso[i], Ahi + g);
            cp16(st + OFF_ALO + aso[i], Alo + g);
        }
        #pragma unroll
        for (int i = 0; i < 4; ++i) {
            size_t g = (size_t)brow[i] * Dn + bc16[i] * 8;
            cp16(st + OFF_BHI + bso[i], Bhi + g);
            cp16(st + OFF_BLO + bso[i], Blo + g);
        }
        CP_COMMIT();
    }

    for (int c = 0; c < NCHUNK; ++c) {
        if (c + 1 < NCHUNK) {
            const uint32_t st = sb + ((c + 1) & 1) * STAGE_BYTES;
            const int dB = (c + 1) * KC;
            #pragma unroll
            for (int i = 0; i < 2; ++i) {
                size_t g = (size_t)arow[i] * Dn + dB + ac16[i] * 8;
                cp16(st + OFF_AHI + aso[i], Ahi + g);
                cp16(st + OFF_ALO + aso[i], Alo + g);
            }
            #pragma unroll
            for (int i = 0; i < 4; ++i) {
                size_t g = (size_t)brow[i] * Dn + dB + bc16[i] * 8;
                cp16(st + OFF_BHI + bso[i], Bhi + g);
                cp16(st + OFF_BLO + bso[i], Blo + g);
            }
            CP_COMMIT();
            CP_WAIT(1);
        } else {
            CP_WAIT(0);
        }
        __syncthreads();

        const uint32_t st = sb + (c & 1) * STAGE_BYTES;
        #pragma unroll
        for (int ks = 0; ks < KC / 16; ++ks) {
            const uint32_t kcol = ks * 32 + colSel;
            uint32_t ahi[4][4], alo[4][4];
            #pragma unroll
            for (int mt = 0; mt < 4; ++mt) {
                uint32_t off = SWZ128(aRowB + (uint32_t)(mt * 16 * 128) + kcol);
                LDSM_X4(ahi[mt][0], ahi[mt][1], ahi[mt][2], ahi[mt][3], st + OFF_AHI + off);
                LDSM_X4(alo[mt][0], alo[mt][1], alo[mt][2], alo[mt][3], st + OFF_ALO + off);
            }
            uint32_t bhi[4][2], blo[4][2];
            #pragma unroll
            for (int p = 0; p < 2; ++p) {
                uint32_t off = SWZ128(bRowB + (uint32_t)(p * 16 * 128) + kcol);
                uint32_t r0, r1, r2, r3;
                LDSM_X4(r0, r1, r2, r3, st + OFF_BHI + off);
                bhi[2*p][0] = r0; bhi[2*p][1] = r2;
                bhi[2*p+1][0] = r1; bhi[2*p+1][1] = r3;
                LDSM_X4(r0, r1, r2, r3, st + OFF_BLO + off);
                blo[2*p][0] = r0; blo[2*p][1] = r2;
                blo[2*p+1][0] = r1; blo[2*p+1][1] = r3;
            }
            #pragma unroll
            for (int mt = 0; mt < 4; ++mt)
                #pragma unroll
                for (int nt = 0; nt < 4; ++nt) {
                    MMA_BF16(acc[mt][nt], ahi[mt], bhi[nt]);
                    MMA_BF16(acc[mt][nt], ahi[mt], blo[nt]);
                    MMA_BF16(acc[mt][nt], alo[mt], bhi[nt]);
                }
        }
        __syncthreads();
    }

    // ---- epilogue: tanh(P + cce) * v, reduce over this CTA's 256 e-cols ----
    const int gRow = lane >> 2;
    const int c2   = (lane & 3) * 2;
    const float* cce = warpM ? s_cce1 : s_cce0;

    #pragma unroll
    for (int mt = 0; mt < 4; ++mt) {
        #pragma unroll
        for (int h2 = 0; h2 < 2; ++h2) {
            float p = 0.f;
            #pragma unroll
            for (int nt = 0; nt < 4; ++nt) {
                int e0 = warpN * 32 + nt * 8 + c2;
                float v0 = acc[mt][nt][h2 * 2 + 0];
                float v1 = acc[mt][nt][h2 * 2 + 1];
                p += tanhfast(v0 + cce[e0    ]) * s_vv[e0    ];
                p += tanhfast(v1 + cce[e0 + 1]) * s_vv[e0 + 1];
            }
            p += __shfl_xor_sync(0xffffffffu, p, 1);
            p += __shfl_xor_sync(0xffffffffu, p, 2);
            if ((lane & 3) == 0) {
                int lrow2 = warpM * 64 + mt * 16 + h2 * 8 + gRow;
                s_red[lrow2 * 8 + warpN] = p;
            }
        }
    }
    __syncthreads();

    if (tid < 128) {
        float s = 0.f;
        #pragma unroll
        for (int x = 0; x < 8; ++x) s += s_red[tid * 8 + x];
        int rg = rowBase + tid;
        int bb = rg >> 6, kk = rg & 63;
        g_upart[et * (Bn * Hn * Kn) + ((bb * Hn + h) << 6) + kk] = s;
    }
}

// -------- K3: sum u partials, mask, softmax over K=64 --------
__global__ void k_softmax(const int* __restrict__ mask, float* __restrict__ out) {
    const int row = blockIdx.x;
    const int k   = threadIdx.x;
    const int b   = row >> 2;
    float s = 0.f;
    #pragma unroll
    for (int nt = 0; nt < NET; ++nt) s += g_upart[nt * (Bn*Hn*Kn) + row * Kn + k];
    if (mask[b * Kn + k] == 0) s = -__int_as_float(0x7f800000);

    __shared__ float sm[64];
    sm[k] = s; __syncthreads();
    #pragma unroll
    for (int o = 32; o; o >>= 1) { if (k < o) sm[k] = fmaxf(sm[k], sm[k+o]); __syncthreads(); }
    float mx = sm[0]; __syncthreads();
    float ex = __expf(s - mx);
    sm[k] = ex; __syncthreads();
    #pragma unroll
    for (int o = 32; o; o >>= 1) { if (k < o) sm[k] += sm[k+o]; __syncthreads(); }
    out[ALPHA_OFF + row * Kn + k] = ex / sm[0];
}

// -------- K4: e_att_heads = alpha @ e_emb  (grid: (D/256) x B) --------
__global__ void k_eah(const float* __restrict__ e_emb, const float* __restrict__ out) {
    const int b = blockIdx.y, tid = threadIdx.x;
    const int d = blockIdx.x * 256 + tid;
    __shared__ float sal[Hn * Kn];
    sal[tid] = out[ALPHA_OFF + b * (Hn*Kn) + tid];
    __syncthreads();
    float a0 = 0.f, a1 = 0.f, a2 = 0.f, a3 = 0.f;
    const float* ep = e_emb + (size_t)b * Kn * Dn + d;
    #pragma unroll 8
    for (int k = 0; k < Kn; ++k) {
        float ev = ep[k * Dn];
        a0 = fmaf(sal[k      ], ev, a0);
        a1 = fmaf(sal[64  + k], ev, a1);
        a2 = fmaf(sal[128 + k], ev, a2);
        a3 = fmaf(sal[192 + k], ev, a3);
    }
    g_eah[(b*Hn + 0) * Dn + d] = a0;
    g_eah[(b*Hn + 1) * Dn + d] = a1;
    g_eah[(b*Hn + 2) * Dn + d] = a2;
    g_eah[(b*Hn + 3) * Dn + d] = a3;
}

// -------- K5: gate logits + softmax over H --------
__global__ void k_gate(const float* __restrict__ c_out, const float* __restrict__ gate_w,
                       const float* __restrict__ gate_b, float* __restrict__ out) {
    const int b = blockIdx.x, tid = threadIdx.x;
    float pv[5] = {0.f, 0.f, 0.f, 0.f, 0.f};
    for (int d = tid; d < Dn; d += 256) {
        float gwc = gate_w[d], gwe = gate_w[Dn + d];
        pv[0] = fmaf(c_out[b*Dn + d], gwc, pv[0]);
        pv[1] = fmaf(g_eah[(b*Hn + 0)*Dn + d], gwe, pv[1]);
        pv[2] = fmaf(g_eah[(b*Hn + 1)*Dn + d], gwe, pv[2]);
        pv[3] = fmaf(g_eah[(b*Hn + 2)*Dn + d], gwe, pv[3]);
        pv[4] = fmaf(g_eah[(b*Hn + 3)*Dn + d], gwe, pv[4]);
    }
    __shared__ float red[256];
    __shared__ float vals[5];
    for (int i = 0; i < 5; ++i) {
        red[tid] = pv[i]; __syncthreads();
        #pragma unroll
        for (int o = 128; o; o >>= 1) { if (tid < o) red[tid] += red[tid+o]; __syncthreads(); }
        if (!tid) vals[i] = red[0];
        __syncthreads();
    }
    if (!tid) {
        float gb = gate_b[0];
        float g0 = vals[0] + vals[1] + gb, g1 = vals[0] + vals[2] + gb;
        float g2 = vals[0] + vals[3] + gb, g3 = vals[0] + vals[4] + gb;
        float mx = fmaxf(fmaxf(g0, g1), fmaxf(g2, g3));
        float e0 = __expf(g0 - mx), e1 = __expf(g1 - mx);
        float e2 = __expf(g2 - mx), e3 = __expf(g3 - mx);
        float inv = 1.f / (e0 + e1 + e2 + e3);
        float hw0 = e0*inv, hw1 = e1*inv, hw2 = e2*inv, hw3 = e3*inv;
        g_hw[b*Hn + 0] = hw0; g_hw[b*Hn + 1] = hw1;
        g_hw[b*Hn + 2] = hw2; g_hw[b*Hn + 3] = hw3;
        out[HW_OFF + b*Hn + 0] = hw0; out[HW_OFF + b*Hn + 1] = hw1;
        out[HW_OFF + b*Hn + 2] = hw2; out[HW_OFF + b*Hn + 3] = hw3;
    }
}

// -------- K6: feature vector [c, e_att, |c-e|, c*e] --------
__global__ void k_feat(const float* __restrict__ c_out) {
    const int b = blockIdx.y;
    const int d = blockIdx.x * 256 + threadIdx.x;
    float hw0 = g_hw[b*Hn+0], hw1 = g_hw[b*Hn+1], hw2 = g_hw[b*Hn+2], hw3 = g_hw[b*Hn+3];
    float ea = hw0 * g_eah[(b*Hn+0)*Dn + d] + hw1 * g_eah[(b*Hn+1)*Dn + d]
             + hw2 * g_eah[(b*Hn+2)*Dn + d] + hw3 * g_eah[(b*Hn+3)*Dn + d];
    float c = c_out[b*Dn + d];
    const int base = b * 4 * Dn;
    g_feat[base +        d] = c;
    g_feat[base +   Dn + d] = ea;
    g_feat[base + 2*Dn + d] = fabsf(c - ea);
    g_feat[base + 3*Dn + d] = c * ea;
}

// -------- K7: hid_pre = feat @ w1.T  (split-k=4, deterministic) --------
#define M2 64
#define N2 64
#define K2 16
__global__ void __launch_bounds__(256)
k_mlp1(const float* __restrict__ w1) {
    __shared__ float A2[K2][M2];
    __shared__ float B2[K2][N2];
    const int tid = threadIdx.x;
    const int oBase = blockIdx.x * N2;
    const int rBase = blockIdx.y * M2;
    const int kBase = blockIdx.z * 1024;
    const int ty = tid >> 4, tx = tid & 15;
    const int lr = tid >> 2;
    const int lk = (tid & 3) * 4;

    const float* Ag = g_feat + (rBase + lr) * (4*Dn) + kBase + lk;
    const float* Bg = w1     + (oBase + lr) * (4*Dn) + kBase + lk;

    float acc[4][4];
    #pragma unroll
    for (int i = 0; i < 4; ++i)
        #pragma unroll
        for (int j = 0; j < 4; ++j) acc[i][j] = 0.f;

    for (int kt = 0; kt < 1024; kt += K2) {
        float4 a4 = *(const float4*)(Ag + kt);
        float4 b4 = *(const float4*)(Bg + kt);
        __syncthreads();
        A2[lk+0][lr] = a4.x; A2[lk+1][lr] = a4.y; A2[lk+2][lr] = a4.z; A2[lk+3][lr] = a4.w;
        B2[lk+0][lr] = b4.x; B2[lk+1][lr] = b4.y; B2[lk+2][lr] = b4.z; B2[lk+3][lr] = b4.w;
        __syncthreads();
        #pragma unroll
        for (int kk = 0; kk < K2; ++kk) {
            float4 av = *(const float4*)&A2[kk][ty*4];
            float4 bv = *(const float4*)&B2[kk][tx*4];
            float a_[4] = {av.x, av.y, av.z, av.w};
            float b_[4] = {bv.x, bv.y, bv.z, bv.w};
            #pragma unroll
            for (int i = 0; i < 4; ++i)
                #pragma unroll
                for (int j = 0; j < 4; ++j)
                    acc[i][j] = fmaf(a_[i], b_[j], acc[i][j]);
        }
    }
    #pragma unroll
    for (int i = 0; i < 4; ++i)
        #pragma unroll
        for (int j = 0; j < 4; ++j)
            g_hidpart[blockIdx.z * (Bn*Dn) + (rBase + ty*4 + i) * Dn + oBase + tx*4 + j] = acc[i][j];
}

// -------- K8: relu(hid_pre + b1) @ w2.T + b2 -> logits --------
__global__ void k_logits(const float* __restrict__ b1, const float* __restrict__ w2,
                         const float* __restrict__ b2, float* __restrict__ out) {
    const int b = blockIdx.x, tid = threadIdx.x;
    float a0 = 0.f, a1 = 0.f, a2 = 0.f;
    for (int d = tid; d < Dn; d += 128) {
        float hp = g_hidpart[            b*Dn + d] + g_hidpart[  Bn*Dn + b*Dn + d]
                 + g_hidpart[2*Bn*Dn +   b*Dn + d] + g_hidpart[3*Bn*Dn + b*Dn + d]
                 + b1[d];
        hp = fmaxf(hp, 0.f);
        a0 = fmaf(hp, w2[        d], a0);
        a1 = fmaf(hp, w2[  Dn + d], a1);
        a2 = fmaf(hp, w2[2*Dn + d], a2);
    }
    __shared__ float red[128];
    __shared__ float vals[3];
    float pv[3] = {a0, a1, a2};
    for (int i = 0; i < 3; ++i) {
        red[tid] = pv[i]; __syncthreads();
        #pragma unroll
        for (int o = 64; o; o >>= 1) { if (tid < o) red[tid] += red[tid+o]; __syncthreads(); }
        if (!tid) vals[i] = red[0];
        __syncthreads();
    }
    if (!tid) {
        out[b*NLn + 0] = vals[0] + b2[0];
        out[b*NLn + 1] = vals[1] + b2[1];
        out[b*NLn + 2] = vals[2] + b2[2];
    }
}

extern "C" void kernel_launch(void* const* d_in, const int* in_sizes, int n_in,
                              void* d_out, int out_size) {
    const float* c_out  = (const float*)d_in[0];
    const float* e_emb  = (const float*)d_in[1];
    const int*   emask  = (const int*)  d_in[2];
    const float* W_c    = (const float*)d_in[3];
    const float* W_e    = (const float*)d_in[4];
    const float* v      = (const float*)d_in[5];
    const float* gate_w = (const float*)d_in[6];
    const float* gate_b = (const float*)d_in[7];
    const float* w1     = (const float*)d_in[8];
    const float* b1     = (const float*)d_in[9];
    const float* w2     = (const float*)d_in[10];
    const float* b2     = (const float*)d_in[11];
    float* out = (float*)d_out;

    cudaFuncSetAttribute(k_attn_mma, cudaFuncAttributeMaxDynamicSharedMemorySize, SMEM_TOTAL);

    k_cvtE<<<(Bn*Kn*Dn/4 + 255)/256, 256>>>(e_emb);
    k_cvtW<<<dim3(Dn/32, Dn/32, Hn), 256>>>(W_e);
    k_wcsum<<<(Hn*Dn*32 + 255)/256, 256>>>(W_c);
    k_attn_mma<<<dim3(NET, (Bn*Kn)/TCM, Hn), NTHREADS, SMEM_TOTAL>>>(c_out, v);
    k_softmax<<<Bn*Hn, Kn>>>(emask, out);
    k_eah<<<dim3(Dn/256, Bn), 256>>>(e_emb, out);
    k_gate<<<Bn, 256>>>(c_out, gate_w, gate_b, out);
    k_feat<<<dim3(Dn/256, Bn), 256>>>(c_out);
    k_mlp1<<<dim3(Dn/N2, Bn/M2, 4), 256>>>(w1);
    k_logits<<<Bn, 128>>>(b1, w2, b2, out);
}

// round 5
// speedup vs baseline: 1.4179x; 1.4179x over previous
#include <cuda_runtime.h>
#include <cuda_fp16.h>
#include <math.h>
#include <stdint.h>

// Problem shapes
#define Bn  256
#define Kn  64
#define Dn  1024
#define Hn  4
#define NLn 3

// Output layout in d_out (fp32): logits (B*NL), alpha (B*H*K), head_weights (B*H)
#define ALPHA_OFF 768
#define HW_OFF    (768 + Bn*Hn*Kn)

// HMMA GEMM tiling
#define TCM 128                 // rows per CTA tile
#define TCN 256                 // e-cols per CTA tile
#define KC  64                  // K elems per chunk (64 fp16 = 128B row)
#define NCHUNK (Dn / KC)        // 16
#define NET    (Dn / TCN)       // 4 e-tiles
#define NTHREADS 512
#define NSTAGE 3

typedef unsigned long long u64;

// -------- scratch (static device globals; no allocation allowed) --------
__device__ float g_wcsum[Hn * Dn];
__device__ float g_upart[NET * Bn * Hn * Kn];   // 1 MB
__device__ float g_eah[Bn * Hn * Dn];
__device__ float g_hw[Bn * Hn];
__device__ float g_feat[Bn * 4 * Dn];
__device__ float g_hidpart[4 * Bn * Dn];
// fp16 split operands: A = Ahi + Alo (exact to ~22 bits), B single fp16
__device__ __half g_Ehi[Bn * Kn * Dn];   // 32 MB
__device__ __half g_Elo[Bn * Kn * Dn];   // 32 MB
__device__ __half g_Wt[Hn * Dn * Dn];    // 8 MB  (transposed: [h][e][d])

// -------- helpers --------
__device__ __forceinline__ uint32_t smem_u32(const void* p) {
    uint32_t a;
    asm("{ .reg .u64 t; cvta.to.shared.u64 t, %1; cvt.u32.u64 %0, t; }" : "=r"(a) : "l"(p));
    return a;
}
__device__ __forceinline__ float tanhfast(float x) {
    float y; asm("tanh.approx.f32 %0, %1;" : "=f"(y) : "f"(x)); return y;
}
#define SWZ128(o) ((o) ^ (((o) >> 3) & 0x70))

__device__ __forceinline__ void cp16(uint32_t saddr, const void* gptr) {
    asm volatile("cp.async.cg.shared.global [%0], [%1], 16;"
                 :: "r"(saddr), "l"(__cvta_generic_to_global(gptr)) : "memory");
}
#define CP_COMMIT() asm volatile("cp.async.commit_group;" ::: "memory")
#define CP_WAIT(n)  asm volatile("cp.async.wait_group %0;" :: "n"(n) : "memory")

#define LDSM_X4(r0, r1, r2, r3, addr) \
    asm volatile("ldmatrix.sync.aligned.m8n8.x4.shared.b16 {%0,%1,%2,%3}, [%4];" \
                 : "=r"(r0), "=r"(r1), "=r"(r2), "=r"(r3) : "r"(addr))

#define MMA_F16(c, a, b) \
    asm volatile("mma.sync.aligned.m16n8k16.row.col.f32.f16.f16.f32 " \
                 "{%0,%1,%2,%3}, {%4,%5,%6,%7}, {%8,%9}, {%0,%1,%2,%3};" \
                 : "+f"((c)[0]), "+f"((c)[1]), "+f"((c)[2]), "+f"((c)[3]) \
                 : "r"((a)[0]), "r"((a)[1]), "r"((a)[2]), "r"((a)[3]), \
                   "r"((b)[0]), "r"((b)[1]))

// smem stage layout: Ahi(16KB) + Alo(16KB) + B(32KB) = 64KB per stage
#define OFF_AHI 0
#define OFF_ALO 16384
#define OFF_B   32768
#define STAGE_BYTES 65536
#define SM_EXTRA (NSTAGE * STAGE_BYTES)               // epilogue arrays beyond stages
#define SMEM_TOTAL (NSTAGE * STAGE_BYTES + 7168)      // 203776

// -------- K0a: split e_emb into fp16 hi/lo --------
__global__ void k_cvtE(const float* __restrict__ e) {
    size_t i = (size_t)blockIdx.x * 256 + threadIdx.x;   // over float4s
    float4 x = ((const float4*)e)[i];
    __half h0 = __float2half_rn(x.x), h1 = __float2half_rn(x.y);
    __half h2 = __float2half_rn(x.z), h3 = __float2half_rn(x.w);
    __half l0 = __float2half_rn(x.x - __half2float(h0));
    __half l1 = __float2half_rn(x.y - __half2float(h1));
    __half l2 = __float2half_rn(x.z - __half2float(h2));
    __half l3 = __float2half_rn(x.w - __half2float(h3));
    ((__half2*)g_Ehi)[2*i    ] = __halves2half2(h0, h1);
    ((__half2*)g_Ehi)[2*i + 1] = __halves2half2(h2, h3);
    ((__half2*)g_Elo)[2*i    ] = __halves2half2(l0, l1);
    ((__half2*)g_Elo)[2*i + 1] = __halves2half2(l2, l3);
}

// -------- K0b: transpose W_e[h][d][e] -> Wt[h][e][d] fp16 --------
__global__ void k_cvtW(const float* __restrict__ W) {
    __shared__ float t[32][33];
    const int h  = blockIdx.z;
    const int dB = blockIdx.y * 32;
    const int eB = blockIdx.x * 32;
    const int lx = threadIdx.x & 31, ly = threadIdx.x >> 5;  // 32 x 8
    #pragma unroll
    for (int r = 0; r < 4; ++r)
        t[ly + 8*r][lx] = W[((size_t)h*Dn + dB + ly + 8*r) * Dn + eB + lx];
    __syncthreads();
    #pragma unroll
    for (int r = 0; r < 4; ++r) {
        float x = t[lx][ly + 8*r];
        size_t oi = ((size_t)h*Dn + eB + ly + 8*r) * Dn + dB + lx;
        g_Wt[oi] = __float2half_rn(x);
    }
}

// -------- K1: Wc_sum[h,d] = sum_e W_c[h,d,e] --------
__global__ void k_wcsum(const float* __restrict__ W_c) {
    int warp = (blockIdx.x * blockDim.x + threadIdx.x) >> 5;
    int lane = threadIdx.x & 31;
    if (warp >= Hn * Dn) return;
    const float* p = W_c + (size_t)warp * Dn;
    float s = 0.f;
    #pragma unroll 8
    for (int j = lane; j < Dn; j += 32) s += p[j];
    #pragma unroll
    for (int o = 16; o; o >>= 1) s += __shfl_down_sync(0xffffffffu, s, o);
    if (!lane) g_wcsum[warp] = s;
}

// -------- K2: HMMA fused  P = (Ahi+Alo) @ Wt^T ;  u = sum_e tanh(cp+P)*v ----
__global__ void __launch_bounds__(NTHREADS, 1)
k_attn_mma(const float* __restrict__ c_out, const float* __restrict__ v)
{
    extern __shared__ char smem[];
    const uint32_t sb = smem_u32(smem);
    const int tid   = threadIdx.x;
    const int wid   = tid >> 5;
    const int lane  = tid & 31;
    const int warpM = wid >> 3;     // 0..1
    const int warpN = wid & 7;      // 0..7

    const int et      = blockIdx.x;          // 0..3
    const int rowBase = blockIdx.y * TCM;    // global GEMM row base
    const int h       = blockIdx.z;          // 0..3
    const int eBase   = et * TCN;

    const __half* Ahi = g_Ehi + (size_t)rowBase * Dn;
    const __half* Alo = g_Elo + (size_t)rowBase * Dn;
    const __half* Bp  = g_Wt  + ((size_t)h * Dn + eBase) * Dn;

    // epilogue smem region (beyond the stages)
    float* s_cce0 = (float*)(smem + SM_EXTRA);       // 256
    float* s_cce1 = s_cce0 + TCN;                    // 256
    float* s_vv   = s_cce1 + TCN;                    // 256
    float* s_red  = s_vv + TCN;                      // [128][8]

    const int b0 = rowBase >> 6;
    {   // precompute per-column scalars (overlaps with first loads)
        int e = eBase + (tid & 255);
        float wc = g_wcsum[h * Dn + e];
        if (tid < 256) {
            s_cce0[tid] = c_out[b0 * Dn + e] * wc;
            s_vv[tid]   = v[h * Dn + e];
        } else {
            s_cce1[tid - 256] = c_out[(b0 + 1) * Dn + e] * wc;
        }
    }

    // per-thread load mapping: A = 1024 16B segs (hi and lo), B = 2048 segs
    int arow[2], ac16[2]; uint32_t aso[2];
    #pragma unroll
    for (int i = 0; i < 2; ++i) {
        int seg = tid + i * NTHREADS;
        arow[i] = seg >> 3; ac16[i] = seg & 7;
        aso[i] = SWZ128((uint32_t)(arow[i] * 128 + ac16[i] * 16));
    }
    int brow[4], bc16[4]; uint32_t bso[4];
    #pragma unroll
    for (int i = 0; i < 4; ++i) {
        int seg = tid + i * NTHREADS;
        brow[i] = seg >> 3; bc16[i] = seg & 7;
        bso[i] = SWZ128((uint32_t)(brow[i] * 128 + bc16[i] * 16));
    }

    float acc[4][4][4];
    #pragma unroll
    for (int mt = 0; mt < 4; ++mt)
        #pragma unroll
        for (int nt = 0; nt < 4; ++nt)
            #pragma unroll
            for (int j = 0; j < 4; ++j) acc[mt][nt][j] = 0.f;

    // ldmatrix base offsets
    const uint32_t aRowB = (uint32_t)((warpM * 64 + (lane & 15)) * 128);
    const uint32_t bRowB = (uint32_t)((warpN * 32 + (lane & 15)) * 128);
    const uint32_t colSel = (uint32_t)((lane >> 4) * 16);

    // prologue: issue chunks 0 and 1 (one commit group each)
    #pragma unroll
    for (int pc = 0; pc < 2; ++pc) {
        const uint32_t st = sb + pc * STAGE_BYTES;
        const int dB = pc * KC;
        #pragma unroll
        for (int i = 0; i < 2; ++i) {
            size_t g = (size_t)arow[i] * Dn + dB + ac16[i] * 8;
            cp16(st + OFF_AHI + aso[i], Ahi + g);
            cp16(st + OFF_ALO + aso[i], Alo + g);
        }
        #pragma unroll
        for (int i = 0; i < 4; ++i) {
            size_t g = (size_t)brow[i] * Dn + dB + bc16[i] * 8;
            cp16(st + OFF_B + bso[i], Bp + g);
        }
        CP_COMMIT();
    }

    int stage = 0;
    for (int c = 0; c < NCHUNK; ++c) {
        if (c + 2 < NCHUNK) { CP_WAIT(1); } else { CP_WAIT(0); }
        __syncthreads();

        const uint32_t st = sb + stage * STAGE_BYTES;
        #pragma unroll
        for (int ks = 0; ks < KC / 16; ++ks) {
            const uint32_t kcol = ks * 32 + colSel;
            uint32_t ahi[4][4], alo[4][4];
            #pragma unroll
            for (int mt = 0; mt < 4; ++mt) {
                uint32_t off = SWZ128(aRowB + (uint32_t)(mt * 16 * 128) + kcol);
                LDSM_X4(ahi[mt][0], ahi[mt][1], ahi[mt][2], ahi[mt][3], st + OFF_AHI + off);
                LDSM_X4(alo[mt][0], alo[mt][1], alo[mt][2], alo[mt][3], st + OFF_ALO + off);
            }
            uint32_t bf[4][2];
            #pragma unroll
            for (int p = 0; p < 2; ++p) {
                uint32_t off = SWZ128(bRowB + (uint32_t)(p * 16 * 128) + kcol);
                uint32_t r0, r1, r2, r3;
                LDSM_X4(r0, r1, r2, r3, st + OFF_B + off);
                bf[2*p][0] = r0; bf[2*p][1] = r2;
                bf[2*p+1][0] = r1; bf[2*p+1][1] = r3;
            }
            #pragma unroll
            for (int mt = 0; mt < 4; ++mt)
                #pragma unroll
                for (int nt = 0; nt < 4; ++nt) {
                    MMA_F16(acc[mt][nt], ahi[mt], bf[nt]);
                    MMA_F16(acc[mt][nt], alo[mt], bf[nt]);
                }
        }

        // issue chunk c+2 into the stage all warps finished reading last iter
        if (c + 2 < NCHUNK) {
            int ns = stage + 2; if (ns >= NSTAGE) ns -= NSTAGE;
            const uint32_t stn = sb + ns * STAGE_BYTES;
            const int dB = (c + 2) * KC;
            #pragma unroll
            for (int i = 0; i < 2; ++i) {
                size_t g = (size_t)arow[i] * Dn + dB + ac16[i] * 8;
                cp16(stn + OFF_AHI + aso[i], Ahi + g);
                cp16(stn + OFF_ALO + aso[i], Alo + g);
            }
            #pragma unroll
            for (int i = 0; i < 4; ++i) {
                size_t g = (size_t)brow[i] * Dn + dB + bc16[i] * 8;
                cp16(stn + OFF_B + bso[i], Bp + g);
            }
            CP_COMMIT();
        }
        if (++stage == NSTAGE) stage = 0;
    }

    // ---- epilogue: tanh(P + cce) * v, reduce over this CTA's 256 e-cols ----
    const int gRow = lane >> 2;
    const int c2   = (lane & 3) * 2;
    const float* cce = warpM ? s_cce1 : s_cce0;

    #pragma unroll
    for (int mt = 0; mt < 4; ++mt) {
        #pragma unroll
        for (int h2 = 0; h2 < 2; ++h2) {
            float p = 0.f;
            #pragma unroll
            for (int nt = 0; nt < 4; ++nt) {
                int e0 = warpN * 32 + nt * 8 + c2;
                float v0 = acc[mt][nt][h2 * 2 + 0];
                float v1 = acc[mt][nt][h2 * 2 + 1];
                p += tanhfast(v0 + cce[e0    ]) * s_vv[e0    ];
                p += tanhfast(v1 + cce[e0 + 1]) * s_vv[e0 + 1];
            }
            p += __shfl_xor_sync(0xffffffffu, p, 1);
            p += __shfl_xor_sync(0xffffffffu, p, 2);
            if ((lane & 3) == 0) {
                int lrow2 = warpM * 64 + mt * 16 + h2 * 8 + gRow;
                s_red[lrow2 * 8 + warpN] = p;
            }
        }
    }
    __syncthreads();

    if (tid < 128) {
        float s = 0.f;
        #pragma unroll
        for (int x = 0; x < 8; ++x) s += s_red[tid * 8 + x];
        int rg = rowBase + tid;
        int bb = rg >> 6, kk = rg & 63;
        g_upart[et * (Bn * Hn * Kn) + ((bb * Hn + h) << 6) + kk] = s;
    }
}

// -------- K3: sum u partials, mask, softmax over K=64 --------
__global__ void k_softmax(const int* __restrict__ mask, float* __restrict__ out) {
    const int row = blockIdx.x;
    const int k   = threadIdx.x;
    const int b   = row >> 2;
    float s = 0.f;
    #pragma unroll
    for (int nt = 0; nt < NET; ++nt) s += g_upart[nt * (Bn*Hn*Kn) + row * Kn + k];
    if (mask[b * Kn + k] == 0) s = -__int_as_float(0x7f800000);

    __shared__ float sm[64];
    sm[k] = s; __syncthreads();
    #pragma unroll
    for (int o = 32; o; o >>= 1) { if (k < o) sm[k] = fmaxf(sm[k], sm[k+o]); __syncthreads(); }
    float mx = sm[0]; __syncthreads();
    float ex = __expf(s - mx);
    sm[k] = ex; __syncthreads();
    #pragma unroll
    for (int o = 32; o; o >>= 1) { if (k < o) sm[k] += sm[k+o]; __syncthreads(); }
    out[ALPHA_OFF + row * Kn + k] = ex / sm[0];
}

// -------- K4: e_att_heads = alpha @ e_emb  (grid: (D/256) x B) --------
__global__ void k_eah(const float* __restrict__ e_emb, const float* __restrict__ out) {
    const int b = blockIdx.y, tid = threadIdx.x;
    const int d = blockIdx.x * 256 + tid;
    __shared__ float sal[Hn * Kn];
    sal[tid] = out[ALPHA_OFF + b * (Hn*Kn) + tid];
    __syncthreads();
    float a0 = 0.f, a1 = 0.f, a2 = 0.f, a3 = 0.f;
    const float* ep = e_emb + (size_t)b * Kn * Dn + d;
    #pragma unroll 8
    for (int k = 0; k < Kn; ++k) {
        float ev = ep[k * Dn];
        a0 = fmaf(sal[k      ], ev, a0);
        a1 = fmaf(sal[64  + k], ev, a1);
        a2 = fmaf(sal[128 + k], ev, a2);
        a3 = fmaf(sal[192 + k], ev, a3);
    }
    g_eah[(b*Hn + 0) * Dn + d] = a0;
    g_eah[(b*Hn + 1) * Dn + d] = a1;
    g_eah[(b*Hn + 2) * Dn + d] = a2;
    g_eah[(b*Hn + 3) * Dn + d] = a3;
}

// -------- K5: gate logits + softmax over H --------
__global__ void k_gate(const float* __restrict__ c_out, const float* __restrict__ gate_w,
                       const float* __restrict__ gate_b, float* __restrict__ out) {
    const int b = blockIdx.x, tid = threadIdx.x;
    float pv[5] = {0.f, 0.f, 0.f, 0.f, 0.f};
    for (int d = tid; d < Dn; d += 256) {
        float gwc = gate_w[d], gwe = gate_w[Dn + d];
        pv[0] = fmaf(c_out[b*Dn + d], gwc, pv[0]);
        pv[1] = fmaf(g_eah[(b*Hn + 0)*Dn + d], gwe, pv[1]);
        pv[2] = fmaf(g_eah[(b*Hn + 1)*Dn + d], gwe, pv[2]);
        pv[3] = fmaf(g_eah[(b*Hn + 2)*Dn + d], gwe, pv[3]);
        pv[4] = fmaf(g_eah[(b*Hn + 3)*Dn + d], gwe, pv[4]);
    }
    __shared__ float red[256];
    __shared__ float vals[5];
    for (int i = 0; i < 5; ++i) {
        red[tid] = pv[i]; __syncthreads();
        #pragma unroll
        for (int o = 128; o; o >>= 1) { if (tid < o) red[tid] += red[tid+o]; __syncthreads(); }
        if (!tid) vals[i] = red[0];
        __syncthreads();
    }
    if (!tid) {
        float gb = gate_b[0];
        float g0 = vals[0] + vals[1] + gb, g1 = vals[0] + vals[2] + gb;
        float g2 = vals[0] + vals[3] + gb, g3 = vals[0] + vals[4] + gb;
        float mx = fmaxf(fmaxf(g0, g1), fmaxf(g2, g3));
        float e0 = __expf(g0 - mx), e1 = __expf(g1 - mx);
        float e2 = __expf(g2 - mx), e3 = __expf(g3 - mx);
        float inv = 1.f / (e0 + e1 + e2 + e3);
        float hw0 = e0*inv, hw1 = e1*inv, hw2 = e2*inv, hw3 = e3*inv;
        g_hw[b*Hn + 0] = hw0; g_hw[b*Hn + 1] = hw1;
        g_hw[b*Hn + 2] = hw2; g_hw[b*Hn + 3] = hw3;
        out[HW_OFF + b*Hn + 0] = hw0; out[HW_OFF + b*Hn + 1] = hw1;
        out[HW_OFF + b*Hn + 2] = hw2; out[HW_OFF + b*Hn + 3] = hw3;
    }
}

// -------- K6: feature vector [c, e_att, |c-e|, c*e] --------
__global__ void k_feat(const float* __restrict__ c_out) {
    const int b = blockIdx.y;
    const int d = blockIdx.x * 256 + threadIdx.x;
    float hw0 = g_hw[b*Hn+0], hw1 = g_hw[b*Hn+1], hw2 = g_hw[b*Hn+2], hw3 = g_hw[b*Hn+3];
    float ea = hw0 * g_eah[(b*Hn+0)*Dn + d] + hw1 * g_eah[(b*Hn+1)*Dn + d]
             + hw2 * g_eah[(b*Hn+2)*Dn + d] + hw3 * g_eah[(b*Hn+3)*Dn + d];
    float c = c_out[b*Dn + d];
    const int base = b * 4 * Dn;
    g_feat[base +        d] = c;
    g_feat[base +   Dn + d] = ea;
    g_feat[base + 2*Dn + d] = fabsf(c - ea);
    g_feat[base + 3*Dn + d] = c * ea;
}

// -------- K7: hid_pre = feat @ w1.T  (split-k=4, deterministic) --------
#define M2 64
#define N2 64
#define K2 16
__global__ void __launch_bounds__(256)
k_mlp1(const float* __restrict__ w1) {
    __shared__ float A2[K2][M2];
    __shared__ float B2[K2][N2];
    const int tid = threadIdx.x;
    const int oBase = blockIdx.x * N2;
    const int rBase = blockIdx.y * M2;
    const int kBase = blockIdx.z * 1024;
    const int ty = tid >> 4, tx = tid & 15;
    const int lr = tid >> 2;
    const int lk = (tid & 3) * 4;

    const float* Ag = g_feat + (rBase + lr) * (4*Dn) + kBase + lk;
    const float* Bg = w1     + (oBase + lr) * (4*Dn) + kBase + lk;

    float acc[4][4];
    #pragma unroll
    for (int i = 0; i < 4; ++i)
        #pragma unroll
        for (int j = 0; j < 4; ++j) acc[i][j] = 0.f;

    for (int kt = 0; kt < 1024; kt += K2) {
        float4 a4 = *(const float4*)(Ag + kt);
        float4 b4 = *(const float4*)(Bg + kt);
        __syncthreads();
        A2[lk+0][lr] = a4.x; A2[lk+1][lr] = a4.y; A2[lk+2][lr] = a4.z; A2[lk+3][lr] = a4.w;
        B2[lk+0][lr] = b4.x; B2[lk+1][lr] = b4.y; B2[lk+2][lr] = b4.z; B2[lk+3][lr] = b4.w;
        __syncthreads();
        #pragma unroll
        for (int kk = 0; kk < K2; ++kk) {
            float4 av = *(const float4*)&A2[kk][ty*4];
            float4 bv = *(const float4*)&B2[kk][tx*4];
            float a_[4] = {av.x, av.y, av.z, av.w};
            float b_[4] = {bv.x, bv.y, bv.z, bv.w};
            #pragma unroll
            for (int i = 0; i < 4; ++i)
                #pragma unroll
                for (int j = 0; j < 4; ++j)
                    acc[i][j] = fmaf(a_[i], b_[j], acc[i][j]);
        }
    }
    #pragma unroll
    for (int i = 0; i < 4; ++i)
        #pragma unroll
        for (int j = 0; j < 4; ++j)
            g_hidpart[blockIdx.z * (Bn*Dn) + (rBase + ty*4 + i) * Dn + oBase + tx*4 + j] = acc[i][j];
}

// -------- K8: relu(hid_pre + b1) @ w2.T + b2 -> logits --------
__global__ void k_logits(const float* __restrict__ b1, const float* __restrict__ w2,
                         const float* __restrict__ b2, float* __restrict__ out) {
    const int b = blockIdx.x, tid = threadIdx.x;
    float a0 = 0.f, a1 = 0.f, a2 = 0.f;
    for (int d = tid; d < Dn; d += 128) {
        float hp = g_hidpart[            b*Dn + d] + g_hidpart[  Bn*Dn + b*Dn + d]
                 + g_hidpart[2*Bn*Dn +   b*Dn + d] + g_hidpart[3*Bn*Dn + b*Dn + d]
                 + b1[d];
        hp = fmaxf(hp, 0.f);
        a0 = fmaf(hp, w2[        d], a0);
        a1 = fmaf(hp, w2[  Dn + d], a1);
        a2 = fmaf(hp, w2[2*Dn + d], a2);
    }
    __shared__ float red[128];
    __shared__ float vals[3];
    float pv[3] = {a0, a1, a2};
    for (int i = 0; i < 3; ++i) {
        red[tid] = pv[i]; __syncthreads();
        #pragma unroll
        for (int o = 64; o; o >>= 1) { if (tid < o) red[tid] += red[tid+o]; __syncthreads(); }
        if (!tid) vals[i] = red[0];
        __syncthreads();
    }
    if (!tid) {
        out[b*NLn + 0] = vals[0] + b2[0];
        out[b*NLn + 1] = vals[1] + b2[1];
        out[b*NLn + 2] = vals[2] + b2[2];
    }
}

extern "C" void kernel_launch(void* const* d_in, const int* in_sizes, int n_in,
                              void* d_out, int out_size) {
    const float* c_out  = (const float*)d_in[0];
    const float* e_emb  = (const float*)d_in[1];
    const int*   emask  = (const int*)  d_in[2];
    const float* W_c    = (const float*)d_in[3];
    const float* W_e    = (const float*)d_in[4];
    const float* v      = (const float*)d_in[5];
    const float* gate_w = (const float*)d_in[6];
    const float* gate_b = (const float*)d_in[7];
    const float* w1     = (const float*)d_in[8];
    const float* b1     = (const float*)d_in[9];
    const float* w2     = (const float*)d_in[10];
    const float* b2     = (const float*)d_in[11];
    float* out = (float*)d_out;

    cudaFuncSetAttribute(k_attn_mma, cudaFuncAttributeMaxDynamicSharedMemorySize, SMEM_TOTAL);

    k_cvtE<<<(Bn*Kn*Dn/4 + 255)/256, 256>>>(e_emb);
    k_cvtW<<<dim3(Dn/32, Dn/32, Hn), 256>>>(W_e);
    k_wcsum<<<(Hn*Dn*32 + 255)/256, 256>>>(W_c);
    k_attn_mma<<<dim3(NET, (Bn*Kn)/TCM, Hn), NTHREADS, SMEM_TOTAL>>>(c_out, v);
    k_softmax<<<Bn*Hn, Kn>>>(emask, out);
    k_eah<<<dim3(Dn/256, Bn), 256>>>(e_emb, out);
    k_gate<<<Bn, 256>>>(c_out, gate_w, gate_b, out);
    k_feat<<<dim3(Dn/256, Bn), 256>>>(c_out);
    k_mlp1<<<dim3(Dn/N2, Bn/M2, 4), 256>>>(w1);
    k_logits<<<Bn, 128>>>(b1, w2, b2, out);
}

// round 6
// speedup vs baseline: 2.3111x; 1.6299x over previous
#include <cuda_runtime.h>
#include <cuda_fp16.h>
#include <math.h>
#include <stdint.h>

// Problem shapes
#define Bn  256
#define Kn  64
#define Dn  1024
#define Hn  4
#define NLn 3

// Output layout in d_out (fp32): logits (B*NL), alpha (B*H*K), head_weights (B*H)
#define ALPHA_OFF 768
#define HW_OFF    (768 + Bn*Hn*Kn)

// HMMA GEMM tiling
#define TCM 128                 // rows per CTA tile
#define TCN 256                 // e-cols per CTA tile
#define KC  64                  // K elems per chunk (64 fp16 = 128B row)
#define NCHUNK (Dn / KC)        // 16
#define NET    (Dn / TCN)       // 4 e-tiles
#define NTHREADS 256
#define NSTAGE 3

typedef unsigned long long u64;

// -------- scratch (static device globals; no allocation allowed) --------
__device__ float g_wcsum[Hn * Dn];
__device__ float g_upart[NET * Bn * Hn * Kn];   // 1 MB
__device__ float g_eah[Bn * Hn * Dn];
__device__ float g_hw[Bn * Hn];
__device__ float g_feat[Bn * 4 * Dn];
__device__ float g_hidpart[4 * Bn * Dn];
// fp16 operands (single-rounded)
__device__ __half g_Ef[Bn * Kn * Dn];    // 32 MB
__device__ __half g_Wt[Hn * Dn * Dn];    // 8 MB  (transposed: [h][e][d])

// -------- helpers --------
__device__ __forceinline__ uint32_t smem_u32(const void* p) {
    uint32_t a;
    asm("{ .reg .u64 t; cvta.to.shared.u64 t, %1; cvt.u32.u64 %0, t; }" : "=r"(a) : "l"(p));
    return a;
}
__device__ __forceinline__ float tanhfast(float x) {
    float y; asm("tanh.approx.f32 %0, %1;" : "=f"(y) : "f"(x)); return y;
}
#define SWZ128(o) ((o) ^ (((o) >> 3) & 0x70))

__device__ __forceinline__ void cp16(uint32_t saddr, const void* gptr) {
    asm volatile("cp.async.cg.shared.global [%0], [%1], 16;"
                 :: "r"(saddr), "l"(__cvta_generic_to_global(gptr)) : "memory");
}
#define CP_COMMIT() asm volatile("cp.async.commit_group;" ::: "memory")
#define CP_WAIT(n)  asm volatile("cp.async.wait_group %0;" :: "n"(n) : "memory")

#define LDSM_X4(r0, r1, r2, r3, addr) \
    asm volatile("ldmatrix.sync.aligned.m8n8.x4.shared.b16 {%0,%1,%2,%3}, [%4];" \
                 : "=r"(r0), "=r"(r1), "=r"(r2), "=r"(r3) : "r"(addr))

#define MMA_F16(c, a, b) \
    asm volatile("mma.sync.aligned.m16n8k16.row.col.f32.f16.f16.f32 " \
                 "{%0,%1,%2,%3}, {%4,%5,%6,%7}, {%8,%9}, {%0,%1,%2,%3};" \
                 : "+f"((c)[0]), "+f"((c)[1]), "+f"((c)[2]), "+f"((c)[3]) \
                 : "r"((a)[0]), "r"((a)[1]), "r"((a)[2]), "r"((a)[3]), \
                   "r"((b)[0]), "r"((b)[1]))

// smem stage layout: A(16KB) + B(32KB) = 48KB per stage
#define OFF_A   0
#define OFF_B   16384
#define STAGE_BYTES 49152
#define SM_EXTRA (NSTAGE * STAGE_BYTES)               // epilogue arrays beyond stages
#define SMEM_TOTAL (NSTAGE * STAGE_BYTES + 6144)      // 153600

// -------- K0a: convert e_emb to fp16 --------
__global__ void k_cvtE(const float* __restrict__ e) {
    size_t i = (size_t)blockIdx.x * 256 + threadIdx.x;   // over float4s
    float4 x = ((const float4*)e)[i];
    __half h0 = __float2half_rn(x.x), h1 = __float2half_rn(x.y);
    __half h2 = __float2half_rn(x.z), h3 = __float2half_rn(x.w);
    ((__half2*)g_Ef)[2*i    ] = __halves2half2(h0, h1);
    ((__half2*)g_Ef)[2*i + 1] = __halves2half2(h2, h3);
}

// -------- K0b: transpose W_e[h][d][e] -> Wt[h][e][d] fp16 --------
__global__ void k_cvtW(const float* __restrict__ W) {
    __shared__ float t[32][33];
    const int h  = blockIdx.z;
    const int dB = blockIdx.y * 32;
    const int eB = blockIdx.x * 32;
    const int lx = threadIdx.x & 31, ly = threadIdx.x >> 5;  // 32 x 8
    #pragma unroll
    for (int r = 0; r < 4; ++r)
        t[ly + 8*r][lx] = W[((size_t)h*Dn + dB + ly + 8*r) * Dn + eB + lx];
    __syncthreads();
    #pragma unroll
    for (int r = 0; r < 4; ++r) {
        float x = t[lx][ly + 8*r];
        size_t oi = ((size_t)h*Dn + eB + ly + 8*r) * Dn + dB + lx;
        g_Wt[oi] = __float2half_rn(x);
    }
}

// -------- K1: Wc_sum[h,d] = sum_e W_c[h,d,e] --------
__global__ void k_wcsum(const float* __restrict__ W_c) {
    int warp = (blockIdx.x * blockDim.x + threadIdx.x) >> 5;
    int lane = threadIdx.x & 31;
    if (warp >= Hn * Dn) return;
    const float* p = W_c + (size_t)warp * Dn;
    float s = 0.f;
    #pragma unroll 8
    for (int j = lane; j < Dn; j += 32) s += p[j];
    #pragma unroll
    for (int o = 16; o; o >>= 1) s += __shfl_down_sync(0xffffffffu, s, o);
    if (!lane) g_wcsum[warp] = s;
}

// -------- K2: HMMA fused  P = E @ Wt^T (fp16);  u = sum_e tanh(cp+P)*v ----
// 8 warps, warp tile 64x64 (4 mt x 8 nt)
__global__ void __launch_bounds__(NTHREADS, 1)
k_attn_mma(const float* __restrict__ c_out, const float* __restrict__ v)
{
    extern __shared__ char smem[];
    const uint32_t sb = smem_u32(smem);
    const int tid   = threadIdx.x;
    const int wid   = tid >> 5;
    const int lane  = tid & 31;
    const int warpM = wid >> 2;     // 0..1
    const int warpN = wid & 3;      // 0..3

    const int et      = blockIdx.x;          // 0..3
    const int rowBase = blockIdx.y * TCM;    // global GEMM row base
    const int h       = blockIdx.z;          // 0..3
    const int eBase   = et * TCN;

    const __half* Ap = g_Ef + (size_t)rowBase * Dn;
    const __half* Bp = g_Wt + ((size_t)h * Dn + eBase) * Dn;

    // epilogue smem region (beyond the stages)
    float* s_cce0 = (float*)(smem + SM_EXTRA);       // 256
    float* s_cce1 = s_cce0 + TCN;                    // 256
    float* s_vv   = s_cce1 + TCN;                    // 256
    float* s_red  = s_vv + TCN;                      // [128][4]

    const int b0 = rowBase >> 6;
    {   // precompute per-column scalars (overlaps with first loads)
        int e0 = eBase + tid;
        float wc0 = g_wcsum[h * Dn + e0];
        s_cce0[tid] = c_out[b0 * Dn + e0] * wc0;
        s_cce1[tid] = c_out[(b0 + 1) * Dn + e0] * wc0;
        s_vv[tid]   = v[h * Dn + e0];
    }

    // per-thread load mapping: A = 1024 16B segs, B = 2048 segs
    int arow[4], ac16[4]; uint32_t aso[4];
    #pragma unroll
    for (int i = 0; i < 4; ++i) {
        int seg = tid + i * NTHREADS;
        arow[i] = seg >> 3; ac16[i] = seg & 7;
        aso[i] = SWZ128((uint32_t)(arow[i] * 128 + ac16[i] * 16));
    }
    int brow[8], bc16[8]; uint32_t bso[8];
    #pragma unroll
    for (int i = 0; i < 8; ++i) {
        int seg = tid + i * NTHREADS;
        brow[i] = seg >> 3; bc16[i] = seg & 7;
        bso[i] = SWZ128((uint32_t)(brow[i] * 128 + bc16[i] * 16));
    }

    float acc[4][8][4];
    #pragma unroll
    for (int mt = 0; mt < 4; ++mt)
        #pragma unroll
        for (int nt = 0; nt < 8; ++nt)
            #pragma unroll
            for (int j = 0; j < 4; ++j) acc[mt][nt][j] = 0.f;

    // ldmatrix base offsets
    const uint32_t aRowB = (uint32_t)((warpM * 64 + (lane & 15)) * 128);
    const uint32_t bRowB = (uint32_t)((warpN * 64 + (lane & 15)) * 128);
    const uint32_t colSel = (uint32_t)((lane >> 4) * 16);

    // prologue: issue chunks 0 and 1 (one commit group each)
    #pragma unroll
    for (int pc = 0; pc < 2; ++pc) {
        const uint32_t st = sb + pc * STAGE_BYTES;
        const int dB = pc * KC;
        #pragma unroll
        for (int i = 0; i < 4; ++i)
            cp16(st + OFF_A + aso[i], Ap + (size_t)arow[i] * Dn + dB + ac16[i] * 8);
        #pragma unroll
        for (int i = 0; i < 8; ++i)
            cp16(st + OFF_B + bso[i], Bp + (size_t)brow[i] * Dn + dB + bc16[i] * 8);
        CP_COMMIT();
    }

    int stage = 0;
    for (int c = 0; c < NCHUNK; ++c) {
        if (c + 2 < NCHUNK) { CP_WAIT(1); } else { CP_WAIT(0); }
        __syncthreads();

        const uint32_t st = sb + stage * STAGE_BYTES;
        #pragma unroll
        for (int ks = 0; ks < KC / 16; ++ks) {
            const uint32_t kcol = ks * 32 + colSel;
            uint32_t af[4][4];
            #pragma unroll
            for (int mt = 0; mt < 4; ++mt) {
                uint32_t off = SWZ128(aRowB + (uint32_t)(mt * 16 * 128) + kcol);
                LDSM_X4(af[mt][0], af[mt][1], af[mt][2], af[mt][3], st + OFF_A + off);
            }
            uint32_t bf[8][2];
            #pragma unroll
            for (int p = 0; p < 4; ++p) {
                uint32_t off = SWZ128(bRowB + (uint32_t)(p * 16 * 128) + kcol);
                uint32_t r0, r1, r2, r3;
                LDSM_X4(r0, r1, r2, r3, st + OFF_B + off);
                bf[2*p][0] = r0; bf[2*p][1] = r2;
                bf[2*p+1][0] = r1; bf[2*p+1][1] = r3;
            }
            #pragma unroll
            for (int mt = 0; mt < 4; ++mt)
                #pragma unroll
                for (int nt = 0; nt < 8; ++nt)
                    MMA_F16(acc[mt][nt], af[mt], bf[nt]);
        }

        // issue chunk c+2 into the stage all warps finished reading last iter
        if (c + 2 < NCHUNK) {
            int ns = stage + 2; if (ns >= NSTAGE) ns -= NSTAGE;
            const uint32_t stn = sb + ns * STAGE_BYTES;
            const int dB = (c + 2) * KC;
            #pragma unroll
            for (int i = 0; i < 4; ++i)
                cp16(stn + OFF_A + aso[i], Ap + (size_t)arow[i] * Dn + dB + ac16[i] * 8);
            #pragma unroll
            for (int i = 0; i < 8; ++i)
                cp16(stn + OFF_B + bso[i], Bp + (size_t)brow[i] * Dn + dB + bc16[i] * 8);
            CP_COMMIT();
        }
        if (++stage == NSTAGE) stage = 0;
    }

    // ---- epilogue: tanh(P + cce) * v, reduce over this CTA's 256 e-cols ----
    const int gRow = lane >> 2;
    const int c2   = (lane & 3) * 2;
    const float* cce = warpM ? s_cce1 : s_cce0;

    #pragma unroll
    for (int mt = 0; mt < 4; ++mt) {
        #pragma unroll
        for (int h2 = 0; h2 < 2; ++h2) {
            float p = 0.f;
            #pragma unroll
            for (int nt = 0; nt < 8; ++nt) {
                int e0 = warpN * 64 + nt * 8 + c2;
                float v0 = acc[mt][nt][h2 * 2 + 0];
                float v1 = acc[mt][nt][h2 * 2 + 1];
                p += tanhfast(v0 + cce[e0    ]) * s_vv[e0    ];
                p += tanhfast(v1 + cce[e0 + 1]) * s_vv[e0 + 1];
            }
            p += __shfl_xor_sync(0xffffffffu, p, 1);
            p += __shfl_xor_sync(0xffffffffu, p, 2);
            if ((lane & 3) == 0) {
                int lrow2 = warpM * 64 + mt * 16 + h2 * 8 + gRow;
                s_red[lrow2 * 4 + warpN] = p;
            }
        }
    }
    __syncthreads();

    if (tid < 128) {
        float s = s_red[tid*4] + s_red[tid*4+1] + s_red[tid*4+2] + s_red[tid*4+3];
        int rg = rowBase + tid;
        int bb = rg >> 6, kk = rg & 63;
        g_upart[et * (Bn * Hn * Kn) + ((bb * Hn + h) << 6) + kk] = s;
    }
}

// -------- K3: sum u partials, mask, softmax over K=64 --------
__global__ void k_softmax(const int* __restrict__ mask, float* __restrict__ out) {
    const int row = blockIdx.x;
    const int k   = threadIdx.x;
    const int b   = row >> 2;
    float s = 0.f;
    #pragma unroll
    for (int nt = 0; nt < NET; ++nt) s += g_upart[nt * (Bn*Hn*Kn) + row * Kn + k];
    if (mask[b * Kn + k] == 0) s = -__int_as_float(0x7f800000);

    __shared__ float sm[64];
    sm[k] = s; __syncthreads();
    #pragma unroll
    for (int o = 32; o; o >>= 1) { if (k < o) sm[k] = fmaxf(sm[k], sm[k+o]); __syncthreads(); }
    float mx = sm[0]; __syncthreads();
    float ex = __expf(s - mx);
    sm[k] = ex; __syncthreads();
    #pragma unroll
    for (int o = 32; o; o >>= 1) { if (k < o) sm[k] += sm[k+o]; __syncthreads(); }
    out[ALPHA_OFF + row * Kn + k] = ex / sm[0];
}

// -------- K4: e_att_heads = alpha @ e_emb  (grid: (D/256) x B) --------
__global__ void k_eah(const float* __restrict__ e_emb, const float* __restrict__ out) {
    const int b = blockIdx.y, tid = threadIdx.x;
    const int d = blockIdx.x * 256 + tid;
    __shared__ float sal[Hn * Kn];
    sal[tid] = out[ALPHA_OFF + b * (Hn*Kn) + tid];
    __syncthreads();
    float a0 = 0.f, a1 = 0.f, a2 = 0.f, a3 = 0.f;
    const float* ep = e_emb + (size_t)b * Kn * Dn + d;
    #pragma unroll 8
    for (int k = 0; k < Kn; ++k) {
        float ev = ep[k * Dn];
        a0 = fmaf(sal[k      ], ev, a0);
        a1 = fmaf(sal[64  + k], ev, a1);
        a2 = fmaf(sal[128 + k], ev, a2);
        a3 = fmaf(sal[192 + k], ev, a3);
    }
    g_eah[(b*Hn + 0) * Dn + d] = a0;
    g_eah[(b*Hn + 1) * Dn + d] = a1;
    g_eah[(b*Hn + 2) * Dn + d] = a2;
    g_eah[(b*Hn + 3) * Dn + d] = a3;
}

// -------- K5: gate logits + softmax over H --------
__global__ void k_gate(const float* __restrict__ c_out, const float* __restrict__ gate_w,
                       const float* __restrict__ gate_b, float* __restrict__ out) {
    const int b = blockIdx.x, tid = threadIdx.x;
    float pv[5] = {0.f, 0.f, 0.f, 0.f, 0.f};
    for (int d = tid; d < Dn; d += 256) {
        float gwc = gate_w[d], gwe = gate_w[Dn + d];
        pv[0] = fmaf(c_out[b*Dn + d], gwc, pv[0]);
        pv[1] = fmaf(g_eah[(b*Hn + 0)*Dn + d], gwe, pv[1]);
        pv[2] = fmaf(g_eah[(b*Hn + 1)*Dn + d], gwe, pv[2]);
        pv[3] = fmaf(g_eah[(b*Hn + 2)*Dn + d], gwe, pv[3]);
        pv[4] = fmaf(g_eah[(b*Hn + 3)*Dn + d], gwe, pv[4]);
    }
    __shared__ float red[256];
    __shared__ float vals[5];
    for (int i = 0; i < 5; ++i) {
        red[tid] = pv[i]; __syncthreads();
        #pragma unroll
        for (int o = 128; o; o >>= 1) { if (tid < o) red[tid] += red[tid+o]; __syncthreads(); }
        if (!tid) vals[i] = red[0];
        __syncthreads();
    }
    if (!tid) {
        float gb = gate_b[0];
        float g0 = vals[0] + vals[1] + gb, g1 = vals[0] + vals[2] + gb;
        float g2 = vals[0] + vals[3] + gb, g3 = vals[0] + vals[4] + gb;
        float mx = fmaxf(fmaxf(g0, g1), fmaxf(g2, g3));
        float e0 = __expf(g0 - mx), e1 = __expf(g1 - mx);
        float e2 = __expf(g2 - mx), e3 = __expf(g3 - mx);
        float inv = 1.f / (e0 + e1 + e2 + e3);
        float hw0 = e0*inv, hw1 = e1*inv, hw2 = e2*inv, hw3 = e3*inv;
        g_hw[b*Hn + 0] = hw0; g_hw[b*Hn + 1] = hw1;
        g_hw[b*Hn + 2] = hw2; g_hw[b*Hn + 3] = hw3;
        out[HW_OFF + b*Hn + 0] = hw0; out[HW_OFF + b*Hn + 1] = hw1;
        out[HW_OFF + b*Hn + 2] = hw2; out[HW_OFF + b*Hn + 3] = hw3;
    }
}

// -------- K6: feature vector [c, e_att, |c-e|, c*e] --------
__global__ void k_feat(const float* __restrict__ c_out) {
    const int b = blockIdx.y;
    const int d = blockIdx.x * 256 + threadIdx.x;
    float hw0 = g_hw[b*Hn+0], hw1 = g_hw[b*Hn+1], hw2 = g_hw[b*Hn+2], hw3 = g_hw[b*Hn+3];
    float ea = hw0 * g_eah[(b*Hn+0)*Dn + d] + hw1 * g_eah[(b*Hn+1)*Dn + d]
             + hw2 * g_eah[(b*Hn+2)*Dn + d] + hw3 * g_eah[(b*Hn+3)*Dn + d];
    float c = c_out[b*Dn + d];
    const int base = b * 4 * Dn;
    g_feat[base +        d] = c;
    g_feat[base +   Dn + d] = ea;
    g_feat[base + 2*Dn + d] = fabsf(c - ea);
    g_feat[base + 3*Dn + d] = c * ea;
}

// -------- K7: hid_pre = feat @ w1.T  (split-k=4, deterministic) --------
#define M2 64
#define N2 64
#define K2 16
__global__ void __launch_bounds__(256)
k_mlp1(const float* __restrict__ w1) {
    __shared__ float A2[K2][M2];
    __shared__ float B2[K2][N2];
    const int tid = threadIdx.x;
    const int oBase = blockIdx.x * N2;
    const int rBase = blockIdx.y * M2;
    const int kBase = blockIdx.z * 1024;
    const int ty = tid >> 4, tx = tid & 15;
    const int lr = tid >> 2;
    const int lk = (tid & 3) * 4;

    const float* Ag = g_feat + (rBase + lr) * (4*Dn) + kBase + lk;
    const float* Bg = w1     + (oBase + lr) * (4*Dn) + kBase + lk;

    float acc[4][4];
    #pragma unroll
    for (int i = 0; i < 4; ++i)
        #pragma unroll
        for (int j = 0; j < 4; ++j) acc[i][j] = 0.f;

    for (int kt = 0; kt < 1024; kt += K2) {
        float4 a4 = *(const float4*)(Ag + kt);
        float4 b4 = *(const float4*)(Bg + kt);
        __syncthreads();
        A2[lk+0][lr] = a4.x; A2[lk+1][lr] = a4.y; A2[lk+2][lr] = a4.z; A2[lk+3][lr] = a4.w;
        B2[lk+0][lr] = b4.x; B2[lk+1][lr] = b4.y; B2[lk+2][lr] = b4.z; B2[lk+3][lr] = b4.w;
        __syncthreads();
        #pragma unroll
        for (int kk = 0; kk < K2; ++kk) {
            float4 av = *(const float4*)&A2[kk][ty*4];
            float4 bv = *(const float4*)&B2[kk][tx*4];
            float a_[4] = {av.x, av.y, av.z, av.w};
            float b_[4] = {bv.x, bv.y, bv.z, bv.w};
            #pragma unroll
            for (int i = 0; i < 4; ++i)
                #pragma unroll
                for (int j = 0; j < 4; ++j)
                    acc[i][j] = fmaf(a_[i], b_[j], acc[i][j]);
        }
    }
    #pragma unroll
    for (int i = 0; i < 4; ++i)
        #pragma unroll
        for (int j = 0; j < 4; ++j)
            g_hidpart[blockIdx.z * (Bn*Dn) + (rBase + ty*4 + i) * Dn + oBase + tx*4 + j] = acc[i][j];
}

// -------- K8: relu(hid_pre + b1) @ w2.T + b2 -> logits --------
__global__ void k_logits(const float* __restrict__ b1, const float* __restrict__ w2,
                         const float* __restrict__ b2, float* __restrict__ out) {
    const int b = blockIdx.x, tid = threadIdx.x;
    float a0 = 0.f, a1 = 0.f, a2 = 0.f;
    for (int d = tid; d < Dn; d += 128) {
        float hp = g_hidpart[            b*Dn + d] + g_hidpart[  Bn*Dn + b*Dn + d]
                 + g_hidpart[2*Bn*Dn +   b*Dn + d] + g_hidpart[3*Bn*Dn + b*Dn + d]
                 + b1[d];
        hp = fmaxf(hp, 0.f);
        a0 = fmaf(hp, w2[        d], a0);
        a1 = fmaf(hp, w2[  Dn + d], a1);
        a2 = fmaf(hp, w2[2*Dn + d], a2);
    }
    __shared__ float red[128];
    __shared__ float vals[3];
    float pv[3] = {a0, a1, a2};
    for (int i = 0; i < 3; ++i) {
        red[tid] = pv[i]; __syncthreads();
        #pragma unroll
        for (int o = 64; o; o >>= 1) { if (tid < o) red[tid] += red[tid+o]; __syncthreads(); }
        if (!tid) vals[i] = red[0];
        __syncthreads();
    }
    if (!tid) {
        out[b*NLn + 0] = vals[0] + b2[0];
        out[b*NLn + 1] = vals[1] + b2[1];
        out[b*NLn + 2] = vals[2] + b2[2];
    }
}

extern "C" void kernel_launch(void* const* d_in, const int* in_sizes, int n_in,
                              void* d_out, int out_size) {
    const float* c_out  = (const float*)d_in[0];
    const float* e_emb  = (const float*)d_in[1];
    const int*   emask  = (const int*)  d_in[2];
    const float* W_c    = (const float*)d_in[3];
    const float* W_e    = (const float*)d_in[4];
    const float* v      = (const float*)d_in[5];
    const float* gate_w = (const float*)d_in[6];
    const float* gate_b = (const float*)d_in[7];
    const float* w1     = (const float*)d_in[8];
    const float* b1     = (const float*)d_in[9];
    const float* w2     = (const float*)d_in[10];
    const float* b2     = (const float*)d_in[11];
    float* out = (float*)d_out;

    cudaFuncSetAttribute(k_attn_mma, cudaFuncAttributeMaxDynamicSharedMemorySize, SMEM_TOTAL);

    k_cvtE<<<(Bn*Kn*Dn/4 + 255)/256, 256>>>(e_emb);
    k_cvtW<<<dim3(Dn/32, Dn/32, Hn), 256>>>(W_e);
    k_wcsum<<<(Hn*Dn*32 + 255)/256, 256>>>(W_c);
    k_attn_mma<<<dim3(NET, (Bn*Kn)/TCM, Hn), NTHREADS, SMEM_TOTAL>>>(c_out, v);
    k_softmax<<<Bn*Hn, Kn>>>(emask, out);
    k_eah<<<dim3(Dn/256, Bn), 256>>>(e_emb, out);
    k_gate<<<Bn, 256>>>(c_out, gate_w, gate_b, out);
    k_feat<<<dim3(Dn/256, Bn), 256>>>(c_out);
    k_mlp1<<<dim3(Dn/N2, Bn/M2, 4), 256>>>(w1);
    k_logits<<<Bn, 128>>>(b1, w2, b2, out);
}

// round 7
// speedup vs baseline: 2.3822x; 1.0308x over previous
#include <cuda_runtime.h>
#include <cuda_fp16.h>
#include <math.h>
#include <stdint.h>

// Problem shapes
#define Bn  256
#define Kn  64
#define Dn  1024
#define Hn  4
#define NLn 3

// Output layout in d_out (fp32): logits (B*NL), alpha (B*H*K), head_weights (B*H)
#define ALPHA_OFF 768
#define HW_OFF    (768 + Bn*Hn*Kn)

// HMMA GEMM tiling: CTA 128x256, warp tile 32x64, 16 warps
#define TCM 128
#define TCN 256
#define KC  64                  // K elems per chunk (64 fp16 = 128B row)
#define NCHUNK (Dn / KC)        // 16
#define NET    (Dn / TCN)       // 4 e-tiles
#define NTHREADS 512
#define NSTAGE 3

typedef unsigned long long u64;

// -------- scratch (static device globals; no allocation allowed) --------
__device__ float g_wcsum[Hn * Dn];
__device__ float g_upart[NET * Bn * Hn * Kn];   // 1 MB
__device__ float g_eah[Bn * Hn * Dn];
__device__ float g_feat[Bn * 4 * Dn];
__device__ float g_hidpart[4 * Bn * Dn];
// fp16 operands (single-rounded)
__device__ __half g_Ef[Bn * Kn * Dn];    // 32 MB
__device__ __half g_Wt[Hn * Dn * Dn];    // 8 MB  (transposed: [h][e][d])

// -------- helpers --------
__device__ __forceinline__ uint32_t smem_u32(const void* p) {
    uint32_t a;
    asm("{ .reg .u64 t; cvta.to.shared.u64 t, %1; cvt.u32.u64 %0, t; }" : "=r"(a) : "l"(p));
    return a;
}
__device__ __forceinline__ float tanhfast(float x) {
    float y; asm("tanh.approx.f32 %0, %1;" : "=f"(y) : "f"(x)); return y;
}
#define SWZ128(o) ((o) ^ (((o) >> 3) & 0x70))

__device__ __forceinline__ void cp16(uint32_t saddr, const void* gptr) {
    asm volatile("cp.async.cg.shared.global [%0], [%1], 16;"
                 :: "r"(saddr), "l"(__cvta_generic_to_global(gptr)) : "memory");
}
#define CP_COMMIT() asm volatile("cp.async.commit_group;" ::: "memory")
#define CP_WAIT(n)  asm volatile("cp.async.wait_group %0;" :: "n"(n) : "memory")

#define LDSM_X4(r0, r1, r2, r3, addr) \
    asm volatile("ldmatrix.sync.aligned.m8n8.x4.shared.b16 {%0,%1,%2,%3}, [%4];" \
                 : "=r"(r0), "=r"(r1), "=r"(r2), "=r"(r3) : "r"(addr))

#define MMA_F16(c, a, b) \
    asm volatile("mma.sync.aligned.m16n8k16.row.col.f32.f16.f16.f32 " \
                 "{%0,%1,%2,%3}, {%4,%5,%6,%7}, {%8,%9}, {%0,%1,%2,%3};" \
                 : "+f"((c)[0]), "+f"((c)[1]), "+f"((c)[2]), "+f"((c)[3]) \
                 : "r"((a)[0]), "r"((a)[1]), "r"((a)[2]), "r"((a)[3]), \
                   "r"((b)[0]), "r"((b)[1]))

// smem stage layout: A(16KB) + B(32KB) = 48KB per stage
#define OFF_A   0
#define OFF_B   16384
#define STAGE_BYTES 49152
#define SM_EXTRA (NSTAGE * STAGE_BYTES)               // epilogue arrays beyond stages
#define SMEM_TOTAL (NSTAGE * STAGE_BYTES + 6144)      // 153600

// -------- K0a: convert e_emb to fp16 --------
__global__ void k_cvtE(const float* __restrict__ e) {
    size_t i = (size_t)blockIdx.x * 256 + threadIdx.x;   // over float4s
    float4 x = ((const float4*)e)[i];
    __half h0 = __float2half_rn(x.x), h1 = __float2half_rn(x.y);
    __half h2 = __float2half_rn(x.z), h3 = __float2half_rn(x.w);
    ((__half2*)g_Ef)[2*i    ] = __halves2half2(h0, h1);
    ((__half2*)g_Ef)[2*i + 1] = __halves2half2(h2, h3);
}

// -------- K0b: transpose W_e[h][d][e] -> Wt[h][e][d] fp16 --------
__global__ void k_cvtW(const float* __restrict__ W) {
    __shared__ float t[32][33];
    const int h  = blockIdx.z;
    const int dB = blockIdx.y * 32;
    const int eB = blockIdx.x * 32;
    const int lx = threadIdx.x & 31, ly = threadIdx.x >> 5;  // 32 x 8
    #pragma unroll
    for (int r = 0; r < 4; ++r)
        t[ly + 8*r][lx] = W[((size_t)h*Dn + dB + ly + 8*r) * Dn + eB + lx];
    __syncthreads();
    #pragma unroll
    for (int r = 0; r < 4; ++r) {
        float x = t[lx][ly + 8*r];
        size_t oi = ((size_t)h*Dn + eB + ly + 8*r) * Dn + dB + lx;
        g_Wt[oi] = __float2half_rn(x);
    }
}

// -------- K1: Wc_sum[h,d] = sum_e W_c[h,d,e] --------
__global__ void k_wcsum(const float* __restrict__ W_c) {
    int warp = (blockIdx.x * blockDim.x + threadIdx.x) >> 5;
    int lane = threadIdx.x & 31;
    if (warp >= Hn * Dn) return;
    const float* p = W_c + (size_t)warp * Dn;
    float s = 0.f;
    #pragma unroll 8
    for (int j = lane; j < Dn; j += 32) s += p[j];
    #pragma unroll
    for (int o = 16; o; o >>= 1) s += __shfl_down_sync(0xffffffffu, s, o);
    if (!lane) g_wcsum[warp] = s;
}

// -------- K2: HMMA fused  P = E @ Wt^T (fp16);  u = sum_e tanh(cp+P)*v ----
// 16 warps, warp tile 32x64 (2 mt x 8 nt) -> 4 warps/SMSP for latency hiding
__global__ void __launch_bounds__(NTHREADS, 1)
k_attn_mma(const float* __restrict__ c_out, const float* __restrict__ v)
{
    extern __shared__ char smem[];
    const uint32_t sb = smem_u32(smem);
    const int tid   = threadIdx.x;
    const int wid   = tid >> 5;
    const int lane  = tid & 31;
    const int warpM = wid >> 2;     // 0..3 (32 rows each)
    const int warpN = wid & 3;      // 0..3 (64 cols each)

    const int et      = blockIdx.x;          // 0..3
    const int rowBase = blockIdx.y * TCM;    // global GEMM row base
    const int h       = blockIdx.z;          // 0..3
    const int eBase   = et * TCN;

    const __half* Ap = g_Ef + (size_t)rowBase * Dn;
    const __half* Bp = g_Wt + ((size_t)h * Dn + eBase) * Dn;

    // epilogue smem region (beyond the stages)
    float* s_cce0 = (float*)(smem + SM_EXTRA);       // 256
    float* s_cce1 = s_cce0 + TCN;                    // 256
    float* s_vv   = s_cce1 + TCN;                    // 256
    float* s_red  = s_vv + TCN;                      // [128][4]

    const int b0 = rowBase >> 6;
    {   // precompute per-column scalars (overlaps with first loads)
        int e0 = eBase + (tid & 255);
        float wc0 = g_wcsum[h * Dn + e0];
        if (tid < 256) {
            s_cce0[tid] = c_out[b0 * Dn + e0] * wc0;
            s_vv[tid]   = v[h * Dn + e0];
        } else {
            s_cce1[tid - 256] = c_out[(b0 + 1) * Dn + e0] * wc0;
        }
    }

    // per-thread load mapping: A = 1024 16B segs, B = 2048 segs
    int arow[2], ac16[2]; uint32_t aso[2];
    #pragma unroll
    for (int i = 0; i < 2; ++i) {
        int seg = tid + i * NTHREADS;
        arow[i] = seg >> 3; ac16[i] = seg & 7;
        aso[i] = SWZ128((uint32_t)(arow[i] * 128 + ac16[i] * 16));
    }
    int brow[4], bc16[4]; uint32_t bso[4];
    #pragma unroll
    for (int i = 0; i < 4; ++i) {
        int seg = tid + i * NTHREADS;
        brow[i] = seg >> 3; bc16[i] = seg & 7;
        bso[i] = SWZ128((uint32_t)(brow[i] * 128 + bc16[i] * 16));
    }

    float acc[2][8][4];
    #pragma unroll
    for (int mt = 0; mt < 2; ++mt)
        #pragma unroll
        for (int nt = 0; nt < 8; ++nt)
            #pragma unroll
            for (int j = 0; j < 4; ++j) acc[mt][nt][j] = 0.f;

    // ldmatrix base offsets
    const uint32_t aRowB = (uint32_t)((warpM * 32 + (lane & 15)) * 128);
    const uint32_t bRowB = (uint32_t)((warpN * 64 + (lane & 15)) * 128);
    const uint32_t colSel = (uint32_t)((lane >> 4) * 16);

    // prologue: issue chunks 0 and 1 (one commit group each)
    #pragma unroll
    for (int pc = 0; pc < 2; ++pc) {
        const uint32_t st = sb + pc * STAGE_BYTES;
        const int dB = pc * KC;
        #pragma unroll
        for (int i = 0; i < 2; ++i)
            cp16(st + OFF_A + aso[i], Ap + (size_t)arow[i] * Dn + dB + ac16[i] * 8);
        #pragma unroll
        for (int i = 0; i < 4; ++i)
            cp16(st + OFF_B + bso[i], Bp + (size_t)brow[i] * Dn + dB + bc16[i] * 8);
        CP_COMMIT();
    }

    int stage = 0;
    for (int c = 0; c < NCHUNK; ++c) {
        if (c + 2 < NCHUNK) { CP_WAIT(1); } else { CP_WAIT(0); }
        __syncthreads();

        const uint32_t st = sb + stage * STAGE_BYTES;
        #pragma unroll
        for (int ks = 0; ks < KC / 16; ++ks) {
            const uint32_t kcol = ks * 32 + colSel;
            uint32_t af[2][4];
            #pragma unroll
            for (int mt = 0; mt < 2; ++mt) {
                uint32_t off = SWZ128(aRowB + (uint32_t)(mt * 16 * 128) + kcol);
                LDSM_X4(af[mt][0], af[mt][1], af[mt][2], af[mt][3], st + OFF_A + off);
            }
            uint32_t bf[8][2];
            #pragma unroll
            for (int p = 0; p < 4; ++p) {
                uint32_t off = SWZ128(bRowB + (uint32_t)(p * 16 * 128) + kcol);
                uint32_t r0, r1, r2, r3;
                LDSM_X4(r0, r1, r2, r3, st + OFF_B + off);
                bf[2*p][0] = r0; bf[2*p][1] = r2;
                bf[2*p+1][0] = r1; bf[2*p+1][1] = r3;
            }
            #pragma unroll
            for (int mt = 0; mt < 2; ++mt)
                #pragma unroll
                for (int nt = 0; nt < 8; ++nt)
                    MMA_F16(acc[mt][nt], af[mt], bf[nt]);
        }

        // issue chunk c+2 into the stage all warps finished reading last iter
        if (c + 2 < NCHUNK) {
            int ns = stage + 2; if (ns >= NSTAGE) ns -= NSTAGE;
            const uint32_t stn = sb + ns * STAGE_BYTES;
            const int dB = (c + 2) * KC;
            #pragma unroll
            for (int i = 0; i < 2; ++i)
                cp16(stn + OFF_A + aso[i], Ap + (size_t)arow[i] * Dn + dB + ac16[i] * 8);
            #pragma unroll
            for (int i = 0; i < 4; ++i)
                cp16(stn + OFF_B + bso[i], Bp + (size_t)brow[i] * Dn + dB + bc16[i] * 8);
            CP_COMMIT();
        }
        if (++stage == NSTAGE) stage = 0;
    }

    // ---- epilogue: tanh(P + cce) * v, reduce over this CTA's 256 e-cols ----
    const int gRow = lane >> 2;
    const int c2   = (lane & 3) * 2;
    const float* cce = (warpM >= 2) ? s_cce1 : s_cce0;

    #pragma unroll
    for (int mt = 0; mt < 2; ++mt) {
        #pragma unroll
        for (int h2 = 0; h2 < 2; ++h2) {
            float p = 0.f;
            #pragma unroll
            for (int nt = 0; nt < 8; ++nt) {
                int e0 = warpN * 64 + nt * 8 + c2;
                float v0 = acc[mt][nt][h2 * 2 + 0];
                float v1 = acc[mt][nt][h2 * 2 + 1];
                p += tanhfast(v0 + cce[e0    ]) * s_vv[e0    ];
                p += tanhfast(v1 + cce[e0 + 1]) * s_vv[e0 + 1];
            }
            p += __shfl_xor_sync(0xffffffffu, p, 1);
            p += __shfl_xor_sync(0xffffffffu, p, 2);
            if ((lane & 3) == 0) {
                int lrow2 = warpM * 32 + mt * 16 + h2 * 8 + gRow;
                s_red[lrow2 * 4 + warpN] = p;
            }
        }
    }
    __syncthreads();

    if (tid < 128) {
        float s = s_red[tid*4] + s_red[tid*4+1] + s_red[tid*4+2] + s_red[tid*4+3];
        int rg = rowBase + tid;
        int bb = rg >> 6, kk = rg & 63;
        g_upart[et * (Bn * Hn * Kn) + ((bb * Hn + h) << 6) + kk] = s;
    }
}

// -------- K3: sum u partials, mask, softmax over K=64 --------
__global__ void k_softmax(const int* __restrict__ mask, float* __restrict__ out) {
    const int row = blockIdx.x;
    const int k   = threadIdx.x;
    const int b   = row >> 2;
    float s = 0.f;
    #pragma unroll
    for (int nt = 0; nt < NET; ++nt) s += g_upart[nt * (Bn*Hn*Kn) + row * Kn + k];
    if (mask[b * Kn + k] == 0) s = -__int_as_float(0x7f800000);

    __shared__ float sm[64];
    sm[k] = s; __syncthreads();
    #pragma unroll
    for (int o = 32; o; o >>= 1) { if (k < o) sm[k] = fmaxf(sm[k], sm[k+o]); __syncthreads(); }
    float mx = sm[0]; __syncthreads();
    float ex = __expf(s - mx);
    sm[k] = ex; __syncthreads();
    #pragma unroll
    for (int o = 32; o; o >>= 1) { if (k < o) sm[k] += sm[k+o]; __syncthreads(); }
    out[ALPHA_OFF + row * Kn + k] = ex / sm[0];
}

// -------- K4: e_att_heads = alpha @ e_emb  (grid: (D/256) x B) --------
__global__ void k_eah(const float* __restrict__ e_emb, const float* __restrict__ out) {
    const int b = blockIdx.y, tid = threadIdx.x;
    const int d = blockIdx.x * 256 + tid;
    __shared__ float sal[Hn * Kn];
    sal[tid] = out[ALPHA_OFF + b * (Hn*Kn) + tid];
    __syncthreads();
    float a0 = 0.f, a1 = 0.f, a2 = 0.f, a3 = 0.f;
    const float* ep = e_emb + (size_t)b * Kn * Dn + d;
    #pragma unroll 8
    for (int k = 0; k < Kn; ++k) {
        float ev = ep[k * Dn];
        a0 = fmaf(sal[k      ], ev, a0);
        a1 = fmaf(sal[64  + k], ev, a1);
        a2 = fmaf(sal[128 + k], ev, a2);
        a3 = fmaf(sal[192 + k], ev, a3);
    }
    g_eah[(b*Hn + 0) * Dn + d] = a0;
    g_eah[(b*Hn + 1) * Dn + d] = a1;
    g_eah[(b*Hn + 2) * Dn + d] = a2;
    g_eah[(b*Hn + 3) * Dn + d] = a3;
}

// -------- K5: gate logits + softmax over H + feature vector (fused) --------
__global__ void k_gate(const float* __restrict__ c_out, const float* __restrict__ gate_w,
                       const float* __restrict__ gate_b, float* __restrict__ out) {
    const int b = blockIdx.x, tid = threadIdx.x;
    float pv[5] = {0.f, 0.f, 0.f, 0.f, 0.f};
    for (int d = tid; d < Dn; d += 256) {
        float gwc = gate_w[d], gwe = gate_w[Dn + d];
        pv[0] = fmaf(c_out[b*Dn + d], gwc, pv[0]);
        pv[1] = fmaf(g_eah[(b*Hn + 0)*Dn + d], gwe, pv[1]);
        pv[2] = fmaf(g_eah[(b*Hn + 1)*Dn + d], gwe, pv[2]);
        pv[3] = fmaf(g_eah[(b*Hn + 2)*Dn + d], gwe, pv[3]);
        pv[4] = fmaf(g_eah[(b*Hn + 3)*Dn + d], gwe, pv[4]);
    }
    __shared__ float red[256];
    __shared__ float vals[5];
    __shared__ float shw[4];
    for (int i = 0; i < 5; ++i) {
        red[tid] = pv[i]; __syncthreads();
        #pragma unroll
        for (int o = 128; o; o >>= 1) { if (tid < o) red[tid] += red[tid+o]; __syncthreads(); }
        if (!tid) vals[i] = red[0];
        __syncthreads();
    }
    if (!tid) {
        float gb = gate_b[0];
        float g0 = vals[0] + vals[1] + gb, g1 = vals[0] + vals[2] + gb;
        float g2 = vals[0] + vals[3] + gb, g3 = vals[0] + vals[4] + gb;
        float mx = fmaxf(fmaxf(g0, g1), fmaxf(g2, g3));
        float e0 = __expf(g0 - mx), e1 = __expf(g1 - mx);
        float e2 = __expf(g2 - mx), e3 = __expf(g3 - mx);
        float inv = 1.f / (e0 + e1 + e2 + e3);
        shw[0] = e0*inv; shw[1] = e1*inv; shw[2] = e2*inv; shw[3] = e3*inv;
        out[HW_OFF + b*Hn + 0] = shw[0]; out[HW_OFF + b*Hn + 1] = shw[1];
        out[HW_OFF + b*Hn + 2] = shw[2]; out[HW_OFF + b*Hn + 3] = shw[3];
    }
    __syncthreads();
    float hw0 = shw[0], hw1 = shw[1], hw2 = shw[2], hw3 = shw[3];
    #pragma unroll
    for (int q = 0; q < 4; ++q) {
        int d = q * 256 + tid;
        float ea = hw0 * g_eah[(b*Hn+0)*Dn + d] + hw1 * g_eah[(b*Hn+1)*Dn + d]
                 + hw2 * g_eah[(b*Hn+2)*Dn + d] + hw3 * g_eah[(b*Hn+3)*Dn + d];
        float c = c_out[b*Dn + d];
        const int base = b * 4 * Dn;
        g_feat[base +        d] = c;
        g_feat[base +   Dn + d] = ea;
        g_feat[base + 2*Dn + d] = fabsf(c - ea);
        g_feat[base + 3*Dn + d] = c * ea;
    }
}

// -------- K7: hid_pre = feat @ w1.T  (split-k=4, deterministic) --------
#define M2 64
#define N2 64
#define K2 16
__global__ void __launch_bounds__(256)
k_mlp1(const float* __restrict__ w1) {
    __shared__ float A2[K2][M2];
    __shared__ float B2[K2][N2];
    const int tid = threadIdx.x;
    const int oBase = blockIdx.x * N2;
    const int rBase = blockIdx.y * M2;
    const int kBase = blockIdx.z * 1024;
    const int ty = tid >> 4, tx = tid & 15;
    const int lr = tid >> 2;
    const int lk = (tid & 3) * 4;

    const float* Ag = g_feat + (rBase + lr) * (4*Dn) + kBase + lk;
    const float* Bg = w1     + (oBase + lr) * (4*Dn) + kBase + lk;

    float acc[4][4];
    #pragma unroll
    for (int i = 0; i < 4; ++i)
        #pragma unroll
        for (int j = 0; j < 4; ++j) acc[i][j] = 0.f;

    for (int kt = 0; kt < 1024; kt += K2) {
        float4 a4 = *(const float4*)(Ag + kt);
        float4 b4 = *(const float4*)(Bg + kt);
        __syncthreads();
        A2[lk+0][lr] = a4.x; A2[lk+1][lr] = a4.y; A2[lk+2][lr] = a4.z; A2[lk+3][lr] = a4.w;
        B2[lk+0][lr] = b4.x; B2[lk+1][lr] = b4.y; B2[lk+2][lr] = b4.z; B2[lk+3][lr] = b4.w;
        __syncthreads();
        #pragma unroll
        for (int kk = 0; kk < K2; ++kk) {
            float4 av = *(const float4*)&A2[kk][ty*4];
            float4 bv = *(const float4*)&B2[kk][tx*4];
            float a_[4] = {av.x, av.y, av.z, av.w};
            float b_[4] = {bv.x, bv.y, bv.z, bv.w};
            #pragma unroll
            for (int i = 0; i < 4; ++i)
                #pragma unroll
                for (int j = 0; j < 4; ++j)
                    acc[i][j] = fmaf(a_[i], b_[j], acc[i][j]);
        }
    }
    #pragma unroll
    for (int i = 0; i < 4; ++i)
        #pragma unroll
        for (int j = 0; j < 4; ++j)
            g_hidpart[blockIdx.z * (Bn*Dn) + (rBase + ty*4 + i) * Dn + oBase + tx*4 + j] = acc[i][j];
}

// -------- K8: relu(hid_pre + b1) @ w2.T + b2 -> logits --------
__global__ void k_logits(const float* __restrict__ b1, const float* __restrict__ w2,
                         const float* __restrict__ b2, float* __restrict__ out) {
    const int b = blockIdx.x, tid = threadIdx.x;
    float a0 = 0.f, a1 = 0.f, a2 = 0.f;
    for (int d = tid; d < Dn; d += 128) {
        float hp = g_hidpart[            b*Dn + d] + g_hidpart[  Bn*Dn + b*Dn + d]
                 + g_hidpart[2*Bn*Dn +   b*Dn + d] + g_hidpart[3*Bn*Dn + b*Dn + d]
                 + b1[d];
        hp = fmaxf(hp, 0.f);
        a0 = fmaf(hp, w2[        d], a0);
        a1 = fmaf(hp, w2[  Dn + d], a1);
        a2 = fmaf(hp, w2[2*Dn + d], a2);
    }
    __shared__ float red[128];
    __shared__ float vals[3];
    float pv[3] = {a0, a1, a2};
    for (int i = 0; i < 3; ++i) {
        red[tid] = pv[i]; __syncthreads();
        #pragma unroll
        for (int o = 64; o; o >>= 1) { if (tid < o) red[tid] += red[tid+o]; __syncthreads(); }
        if (!tid) vals[i] = red[0];
        __syncthreads();
    }
    if (!tid) {
        out[b*NLn + 0] = vals[0] + b2[0];
        out[b*NLn + 1] = vals[1] + b2[1];
        out[b*NLn + 2] = vals[2] + b2[2];
    }
}

extern "C" void kernel_launch(void* const* d_in, const int* in_sizes, int n_in,
                              void* d_out, int out_size) {
    const float* c_out  = (const float*)d_in[0];
    const float* e_emb  = (const float*)d_in[1];
    const int*   emask  = (const int*)  d_in[2];
    const float* W_c    = (const float*)d_in[3];
    const float* W_e    = (const float*)d_in[4];
    const float* v      = (const float*)d_in[5];
    const float* gate_w = (const float*)d_in[6];
    const float* gate_b = (const float*)d_in[7];
    const float* w1     = (const float*)d_in[8];
    const float* b1     = (const float*)d_in[9];
    const float* w2     = (const float*)d_in[10];
    const float* b2     = (const float*)d_in[11];
    float* out = (float*)d_out;

    cudaFuncSetAttribute(k_attn_mma, cudaFuncAttributeMaxDynamicSharedMemorySize, SMEM_TOTAL);

    k_cvtE<<<(Bn*Kn*Dn/4 + 255)/256, 256>>>(e_emb);
    k_cvtW<<<dim3(Dn/32, Dn/32, Hn), 256>>>(W_e);
    k_wcsum<<<(Hn*Dn*32 + 255)/256, 256>>>(W_c);
    k_attn_mma<<<dim3(NET, (Bn*Kn)/TCM, Hn), NTHREADS, SMEM_TOTAL>>>(c_out, v);
    k_softmax<<<Bn*Hn, Kn>>>(emask, out);
    k_eah<<<dim3(Dn/256, Bn), 256>>>(e_emb, out);
    k_gate<<<Bn, 256>>>(c_out, gate_w, gate_b, out);
    k_mlp1<<<dim3(Dn/N2, Bn/M2, 4), 256>>>(w1);
    k_logits<<<Bn, 128>>>(b1, w2, b2, out);
}

// round 8
// speedup vs baseline: 2.5754x; 1.0811x over previous
#include <cuda_runtime.h>
#include <cuda_fp16.h>
#include <math.h>
#include <stdint.h>

// Problem shapes
#define Bn  256
#define Kn  64
#define Dn  1024
#define Hn  4
#define NLn 3

// Output layout in d_out (fp32): logits (B*NL), alpha (B*H*K), head_weights (B*H)
#define ALPHA_OFF 768
#define HW_OFF    (768 + Bn*Hn*Kn)

// HMMA GEMM tiling: CTA 128x128, warp tile 32x64, 8 warps, 2 CTAs/SM
#define TCM 128
#define TCN 128
#define KC  64                  // K elems per chunk (64 fp16 = 128B row)
#define NCHUNK (Dn / KC)        // 16
#define NET    (Dn / TCN)       // 8 e-tiles
#define NTHREADS 256
#define NSTAGE 3

typedef unsigned long long u64;

// -------- scratch (static device globals; no allocation allowed) --------
__device__ float g_wcsum[Hn * Dn];
__device__ float g_upart[NET * Bn * Hn * Kn];   // 2 MB
__device__ float g_eah[Bn * Hn * Dn];
__device__ float g_feat[Bn * 4 * Dn];
__device__ float g_hidpart[4 * Bn * Dn];
// fp16 operands (single-rounded)
__device__ __half g_Ef[Bn * Kn * Dn];    // 32 MB
__device__ __half g_Wt[Hn * Dn * Dn];    // 8 MB  (transposed: [h][e][d])

// -------- helpers --------
__device__ __forceinline__ uint32_t smem_u32(const void* p) {
    uint32_t a;
    asm("{ .reg .u64 t; cvta.to.shared.u64 t, %1; cvt.u32.u64 %0, t; }" : "=r"(a) : "l"(p));
    return a;
}
__device__ __forceinline__ float tanhfast(float x) {
    float y; asm("tanh.approx.f32 %0, %1;" : "=f"(y) : "f"(x)); return y;
}
#define SWZ128(o) ((o) ^ (((o) >> 3) & 0x70))

__device__ __forceinline__ void cp16(uint32_t saddr, const void* gptr) {
    asm volatile("cp.async.cg.shared.global [%0], [%1], 16;"
                 :: "r"(saddr), "l"(__cvta_generic_to_global(gptr)) : "memory");
}
#define CP_COMMIT() asm volatile("cp.async.commit_group;" ::: "memory")
#define CP_WAIT(n)  asm volatile("cp.async.wait_group %0;" :: "n"(n) : "memory")

#define LDSM_X4(r0, r1, r2, r3, addr) \
    asm volatile("ldmatrix.sync.aligned.m8n8.x4.shared.b16 {%0,%1,%2,%3}, [%4];" \
                 : "=r"(r0), "=r"(r1), "=r"(r2), "=r"(r3) : "r"(addr))

#define MMA_F16(c, a, b) \
    asm volatile("mma.sync.aligned.m16n8k16.row.col.f32.f16.f16.f32 " \
                 "{%0,%1,%2,%3}, {%4,%5,%6,%7}, {%8,%9}, {%0,%1,%2,%3};" \
                 : "+f"((c)[0]), "+f"((c)[1]), "+f"((c)[2]), "+f"((c)[3]) \
                 : "r"((a)[0]), "r"((a)[1]), "r"((a)[2]), "r"((a)[3]), \
                   "r"((b)[0]), "r"((b)[1]))

// smem stage layout: A(16KB) + B(16KB) = 32KB per stage
#define OFF_A   0
#define OFF_B   16384
#define STAGE_BYTES 32768
#define SM_EXTRA (NSTAGE * STAGE_BYTES)               // epilogue arrays beyond stages
#define SMEM_TOTAL (NSTAGE * STAGE_BYTES + 4096)      // 102400 -> 2 CTAs/SM

// -------- K0a: convert e_emb to fp16 --------
__global__ void k_cvtE(const float* __restrict__ e) {
    size_t i = (size_t)blockIdx.x * 256 + threadIdx.x;   // over float4s
    float4 x = ((const float4*)e)[i];
    __half h0 = __float2half_rn(x.x), h1 = __float2half_rn(x.y);
    __half h2 = __float2half_rn(x.z), h3 = __float2half_rn(x.w);
    ((__half2*)g_Ef)[2*i    ] = __halves2half2(h0, h1);
    ((__half2*)g_Ef)[2*i + 1] = __halves2half2(h2, h3);
}

// -------- K0b: transpose W_e[h][d][e] -> Wt[h][e][d] fp16 --------
__global__ void k_cvtW(const float* __restrict__ W) {
    __shared__ float t[32][33];
    const int h  = blockIdx.z;
    const int dB = blockIdx.y * 32;
    const int eB = blockIdx.x * 32;
    const int lx = threadIdx.x & 31, ly = threadIdx.x >> 5;  // 32 x 8
    #pragma unroll
    for (int r = 0; r < 4; ++r)
        t[ly + 8*r][lx] = W[((size_t)h*Dn + dB + ly + 8*r) * Dn + eB + lx];
    __syncthreads();
    #pragma unroll
    for (int r = 0; r < 4; ++r) {
        float x = t[lx][ly + 8*r];
        size_t oi = ((size_t)h*Dn + eB + ly + 8*r) * Dn + dB + lx;
        g_Wt[oi] = __float2half_rn(x);
    }
}

// -------- K1: Wc_sum[h,d] = sum_e W_c[h,d,e] --------
__global__ void k_wcsum(const float* __restrict__ W_c) {
    int warp = (blockIdx.x * blockDim.x + threadIdx.x) >> 5;
    int lane = threadIdx.x & 31;
    if (warp >= Hn * Dn) return;
    const float* p = W_c + (size_t)warp * Dn;
    float s = 0.f;
    #pragma unroll 8
    for (int j = lane; j < Dn; j += 32) s += p[j];
    #pragma unroll
    for (int o = 16; o; o >>= 1) s += __shfl_down_sync(0xffffffffu, s, o);
    if (!lane) g_wcsum[warp] = s;
}

// -------- K2: HMMA fused  P = E @ Wt^T (fp16);  u = sum_e tanh(cp+P)*v ----
// 8 warps, warp tile 32x64; 2 CTAs/SM to interleave barrier bubbles
__global__ void __launch_bounds__(NTHREADS, 2)
k_attn_mma(const float* __restrict__ c_out, const float* __restrict__ v)
{
    extern __shared__ char smem[];
    const uint32_t sb = smem_u32(smem);
    const int tid   = threadIdx.x;
    const int wid   = tid >> 5;
    const int lane  = tid & 31;
    const int warpM = wid >> 1;     // 0..3 (32 rows each)
    const int warpN = wid & 1;      // 0..1 (64 cols each)

    const int et      = blockIdx.x;          // 0..7
    const int rowBase = blockIdx.y * TCM;    // global GEMM row base
    const int h       = blockIdx.z;          // 0..3
    const int eBase   = et * TCN;

    const __half* Ap = g_Ef + (size_t)rowBase * Dn;
    const __half* Bp = g_Wt + ((size_t)h * Dn + eBase) * Dn;

    // epilogue smem region (beyond the stages)
    float* s_cce0 = (float*)(smem + SM_EXTRA);       // 128
    float* s_cce1 = s_cce0 + TCN;                    // 128
    float* s_vv   = s_cce1 + TCN;                    // 128
    float* s_red  = s_vv + TCN;                      // [128][2]

    const int b0 = rowBase >> 6;
    {   // precompute per-column scalars (overlaps with first loads)
        int e0 = eBase + (tid & 127);
        float wc0 = g_wcsum[h * Dn + e0];
        if (tid < 128) {
            s_cce0[tid] = c_out[b0 * Dn + e0] * wc0;
            s_vv[tid]   = v[h * Dn + e0];
        } else {
            s_cce1[tid - 128] = c_out[(b0 + 1) * Dn + e0] * wc0;
        }
    }

    // per-thread load mapping: A = 1024 16B segs, B = 1024 segs
    int arow[4], ac16[4]; uint32_t aso[4];
    #pragma unroll
    for (int i = 0; i < 4; ++i) {
        int seg = tid + i * NTHREADS;
        arow[i] = seg >> 3; ac16[i] = seg & 7;
        aso[i] = SWZ128((uint32_t)(arow[i] * 128 + ac16[i] * 16));
    }

    float acc[2][8][4];
    #pragma unroll
    for (int mt = 0; mt < 2; ++mt)
        #pragma unroll
        for (int nt = 0; nt < 8; ++nt)
            #pragma unroll
            for (int j = 0; j < 4; ++j) acc[mt][nt][j] = 0.f;

    // ldmatrix base offsets
    const uint32_t aRowB = (uint32_t)((warpM * 32 + (lane & 15)) * 128);
    const uint32_t bRowB = (uint32_t)((warpN * 64 + (lane & 15)) * 128);
    const uint32_t colSel = (uint32_t)((lane >> 4) * 16);

    // prologue: issue chunks 0 and 1 (one commit group each)
    #pragma unroll
    for (int pc = 0; pc < 2; ++pc) {
        const uint32_t st = sb + pc * STAGE_BYTES;
        const int dB = pc * KC;
        #pragma unroll
        for (int i = 0; i < 4; ++i) {
            cp16(st + OFF_A + aso[i], Ap + (size_t)arow[i] * Dn + dB + ac16[i] * 8);
            cp16(st + OFF_B + aso[i], Bp + (size_t)arow[i] * Dn + dB + ac16[i] * 8);
        }
        CP_COMMIT();
    }

    int stage = 0;
    for (int c = 0; c < NCHUNK; ++c) {
        if (c + 2 < NCHUNK) { CP_WAIT(1); } else { CP_WAIT(0); }
        __syncthreads();

        const uint32_t st = sb + stage * STAGE_BYTES;
        #pragma unroll
        for (int ks = 0; ks < KC / 16; ++ks) {
            const uint32_t kcol = ks * 32 + colSel;
            uint32_t af[2][4];
            #pragma unroll
            for (int mt = 0; mt < 2; ++mt) {
                uint32_t off = SWZ128(aRowB + (uint32_t)(mt * 16 * 128) + kcol);
                LDSM_X4(af[mt][0], af[mt][1], af[mt][2], af[mt][3], st + OFF_A + off);
            }
            uint32_t bf[8][2];
            #pragma unroll
            for (int p = 0; p < 4; ++p) {
                uint32_t off = SWZ128(bRowB + (uint32_t)(p * 16 * 128) + kcol);
                uint32_t r0, r1, r2, r3;
                LDSM_X4(r0, r1, r2, r3, st + OFF_B + off);
                bf[2*p][0] = r0; bf[2*p][1] = r2;
                bf[2*p+1][0] = r1; bf[2*p+1][1] = r3;
            }
            #pragma unroll
            for (int mt = 0; mt < 2; ++mt)
                #pragma unroll
                for (int nt = 0; nt < 8; ++nt)
                    MMA_F16(acc[mt][nt], af[mt], bf[nt]);
        }

        // issue chunk c+2 into the stage all warps finished reading last iter
        if (c + 2 < NCHUNK) {
            int ns = stage + 2; if (ns >= NSTAGE) ns -= NSTAGE;
            const uint32_t stn = sb + ns * STAGE_BYTES;
            const int dB = (c + 2) * KC;
            #pragma unroll
            for (int i = 0; i < 4; ++i) {
                cp16(stn + OFF_A + aso[i], Ap + (size_t)arow[i] * Dn + dB + ac16[i] * 8);
                cp16(stn + OFF_B + aso[i], Bp + (size_t)arow[i] * Dn + dB + ac16[i] * 8);
            }
            CP_COMMIT();
        }
        if (++stage == NSTAGE) stage = 0;
    }

    // ---- epilogue: tanh(P + cce) * v, reduce over this CTA's 128 e-cols ----
    const int gRow = lane >> 2;
    const int c2   = (lane & 3) * 2;
    const float* cce = (warpM >= 2) ? s_cce1 : s_cce0;

    #pragma unroll
    for (int mt = 0; mt < 2; ++mt) {
        #pragma unroll
        for (int h2 = 0; h2 < 2; ++h2) {
            float p = 0.f;
            #pragma unroll
            for (int nt = 0; nt < 8; ++nt) {
                int e0 = warpN * 64 + nt * 8 + c2;
                float v0 = acc[mt][nt][h2 * 2 + 0];
                float v1 = acc[mt][nt][h2 * 2 + 1];
                p += tanhfast(v0 + cce[e0    ]) * s_vv[e0    ];
                p += tanhfast(v1 + cce[e0 + 1]) * s_vv[e0 + 1];
            }
            p += __shfl_xor_sync(0xffffffffu, p, 1);
            p += __shfl_xor_sync(0xffffffffu, p, 2);
            if ((lane & 3) == 0) {
                int lrow2 = warpM * 32 + mt * 16 + h2 * 8 + gRow;
                s_red[lrow2 * 2 + warpN] = p;
            }
        }
    }
    __syncthreads();

    if (tid < 128) {
        float s = s_red[tid*2] + s_red[tid*2+1];
        int rg = rowBase + tid;
        int bb = rg >> 6, kk = rg & 63;
        g_upart[et * (Bn * Hn * Kn) + ((bb * Hn + h) << 6) + kk] = s;
    }
}

// -------- K3: sum u partials, mask, softmax over K=64 --------
__global__ void k_softmax(const int* __restrict__ mask, float* __restrict__ out) {
    const int row = blockIdx.x;
    const int k   = threadIdx.x;
    const int b   = row >> 2;
    float s = 0.f;
    #pragma unroll
    for (int nt = 0; nt < NET; ++nt) s += g_upart[nt * (Bn*Hn*Kn) + row * Kn + k];
    if (mask[b * Kn + k] == 0) s = -__int_as_float(0x7f800000);

    __shared__ float sm[64];
    sm[k] = s; __syncthreads();
    #pragma unroll
    for (int o = 32; o; o >>= 1) { if (k < o) sm[k] = fmaxf(sm[k], sm[k+o]); __syncthreads(); }
    float mx = sm[0]; __syncthreads();
    float ex = __expf(s - mx);
    sm[k] = ex; __syncthreads();
    #pragma unroll
    for (int o = 32; o; o >>= 1) { if (k < o) sm[k] += sm[k+o]; __syncthreads(); }
    out[ALPHA_OFF + row * Kn + k] = ex / sm[0];
}

// -------- K4: e_att_heads = alpha @ e_emb  (grid: (D/256) x B) --------
__global__ void k_eah(const float* __restrict__ e_emb, const float* __restrict__ out) {
    const int b = blockIdx.y, tid = threadIdx.x;
    const int d = blockIdx.x * 256 + tid;
    __shared__ float sal[Hn * Kn];
    sal[tid] = out[ALPHA_OFF + b * (Hn*Kn) + tid];
    __syncthreads();
    float a0 = 0.f, a1 = 0.f, a2 = 0.f, a3 = 0.f;
    const float* ep = e_emb + (size_t)b * Kn * Dn + d;
    #pragma unroll 8
    for (int k = 0; k < Kn; ++k) {
        float ev = ep[k * Dn];
        a0 = fmaf(sal[k      ], ev, a0);
        a1 = fmaf(sal[64  + k], ev, a1);
        a2 = fmaf(sal[128 + k], ev, a2);
        a3 = fmaf(sal[192 + k], ev, a3);
    }
    g_eah[(b*Hn + 0) * Dn + d] = a0;
    g_eah[(b*Hn + 1) * Dn + d] = a1;
    g_eah[(b*Hn + 2) * Dn + d] = a2;
    g_eah[(b*Hn + 3) * Dn + d] = a3;
}

// -------- K5: gate logits + softmax over H + feature vector (fused) --------
__global__ void k_gate(const float* __restrict__ c_out, const float* __restrict__ gate_w,
                       const float* __restrict__ gate_b, float* __restrict__ out) {
    const int b = blockIdx.x, tid = threadIdx.x;
    float pv[5] = {0.f, 0.f, 0.f, 0.f, 0.f};
    for (int d = tid; d < Dn; d += 256) {
        float gwc = gate_w[d], gwe = gate_w[Dn + d];
        pv[0] = fmaf(c_out[b*Dn + d], gwc, pv[0]);
        pv[1] = fmaf(g_eah[(b*Hn + 0)*Dn + d], gwe, pv[1]);
        pv[2] = fmaf(g_eah[(b*Hn + 1)*Dn + d], gwe, pv[2]);
        pv[3] = fmaf(g_eah[(b*Hn + 2)*Dn + d], gwe, pv[3]);
        pv[4] = fmaf(g_eah[(b*Hn + 3)*Dn + d], gwe, pv[4]);
    }
    __shared__ float red[256];
    __shared__ float vals[5];
    __shared__ float shw[4];
    for (int i = 0; i < 5; ++i) {
        red[tid] = pv[i]; __syncthreads();
        #pragma unroll
        for (int o = 128; o; o >>= 1) { if (tid < o) red[tid] += red[tid+o]; __syncthreads(); }
        if (!tid) vals[i] = red[0];
        __syncthreads();
    }
    if (!tid) {
        float gb = gate_b[0];
        float g0 = vals[0] + vals[1] + gb, g1 = vals[0] + vals[2] + gb;
        float g2 = vals[0] + vals[3] + gb, g3 = vals[0] + vals[4] + gb;
        float mx = fmaxf(fmaxf(g0, g1), fmaxf(g2, g3));
        float e0 = __expf(g0 - mx), e1 = __expf(g1 - mx);
        float e2 = __expf(g2 - mx), e3 = __expf(g3 - mx);
        float inv = 1.f / (e0 + e1 + e2 + e3);
        shw[0] = e0*inv; shw[1] = e1*inv; shw[2] = e2*inv; shw[3] = e3*inv;
        out[HW_OFF + b*Hn + 0] = shw[0]; out[HW_OFF + b*Hn + 1] = shw[1];
        out[HW_OFF + b*Hn + 2] = shw[2]; out[HW_OFF + b*Hn + 3] = shw[3];
    }
    __syncthreads();
    float hw0 = shw[0], hw1 = shw[1], hw2 = shw[2], hw3 = shw[3];
    #pragma unroll
    for (int q = 0; q < 4; ++q) {
        int d = q * 256 + tid;
        float ea = hw0 * g_eah[(b*Hn+0)*Dn + d] + hw1 * g_eah[(b*Hn+1)*Dn + d]
                 + hw2 * g_eah[(b*Hn+2)*Dn + d] + hw3 * g_eah[(b*Hn+3)*Dn + d];
        float c = c_out[b*Dn + d];
        const int base = b * 4 * Dn;
        g_feat[base +        d] = c;
        g_feat[base +   Dn + d] = ea;
        g_feat[base + 2*Dn + d] = fabsf(c - ea);
        g_feat[base + 3*Dn + d] = c * ea;
    }
}

// -------- K7: hid_pre = feat @ w1.T  (split-k=4, deterministic) --------
#define M2 64
#define N2 64
#define K2 16
__global__ void __launch_bounds__(256)
k_mlp1(const float* __restrict__ w1) {
    __shared__ float A2[K2][M2];
    __shared__ float B2[K2][N2];
    const int tid = threadIdx.x;
    const int oBase = blockIdx.x * N2;
    const int rBase = blockIdx.y * M2;
    const int kBase = blockIdx.z * 1024;
    const int ty = tid >> 4, tx = tid & 15;
    const int lr = tid >> 2;
    const int lk = (tid & 3) * 4;

    const float* Ag = g_feat + (rBase + lr) * (4*Dn) + kBase + lk;
    const float* Bg = w1     + (oBase + lr) * (4*Dn) + kBase + lk;

    float acc[4][4];
    #pragma unroll
    for (int i = 0; i < 4; ++i)
        #pragma unroll
        for (int j = 0; j < 4; ++j) acc[i][j] = 0.f;

    for (int kt = 0; kt < 1024; kt += K2) {
        float4 a4 = *(const float4*)(Ag + kt);
        float4 b4 = *(const float4*)(Bg + kt);
        __syncthreads();
        A2[lk+0][lr] = a4.x; A2[lk+1][lr] = a4.y; A2[lk+2][lr] = a4.z; A2[lk+3][lr] = a4.w;
        B2[lk+0][lr] = b4.x; B2[lk+1][lr] = b4.y; B2[lk+2][lr] = b4.z; B2[lk+3][lr] = b4.w;
        __syncthreads();
        #pragma unroll
        for (int kk = 0; kk < K2; ++kk) {
            float4 av = *(const float4*)&A2[kk][ty*4];
            float4 bv = *(const float4*)&B2[kk][tx*4];
            float a_[4] = {av.x, av.y, av.z, av.w};
            float b_[4] = {bv.x, bv.y, bv.z, bv.w};
            #pragma unroll
            for (int i = 0; i < 4; ++i)
                #pragma unroll
                for (int j = 0; j < 4; ++j)
                    acc[i][j] = fmaf(a_[i], b_[j], acc[i][j]);
        }
    }
    #pragma unroll
    for (int i = 0; i < 4; ++i)
        #pragma unroll
        for (int j = 0; j < 4; ++j)
            g_hidpart[blockIdx.z * (Bn*Dn) + (rBase + ty*4 + i) * Dn + oBase + tx*4 + j] = acc[i][j];
}

// -------- K8: relu(hid_pre + b1) @ w2.T + b2 -> logits --------
__global__ void k_logits(const float* __restrict__ b1, const float* __restrict__ w2,
                         const float* __restrict__ b2, float* __restrict__ out) {
    const int b = blockIdx.x, tid = threadIdx.x;
    float a0 = 0.f, a1 = 0.f, a2 = 0.f;
    for (int d = tid; d < Dn; d += 128) {
        float hp = g_hidpart[            b*Dn + d] + g_hidpart[  Bn*Dn + b*Dn + d]
                 + g_hidpart[2*Bn*Dn +   b*Dn + d] + g_hidpart[3*Bn*Dn + b*Dn + d]
                 + b1[d];
        hp = fmaxf(hp, 0.f);
        a0 = fmaf(hp, w2[        d], a0);
        a1 = fmaf(hp, w2[  Dn + d], a1);
        a2 = fmaf(hp, w2[2*Dn + d], a2);
    }
    __shared__ float red[128];
    __shared__ float vals[3];
    float pv[3] = {a0, a1, a2};
    for (int i = 0; i < 3; ++i) {
        red[tid] = pv[i]; __syncthreads();
        #pragma unroll
        for (int o = 64; o; o >>= 1) { if (tid < o) red[tid] += red[tid+o]; __syncthreads(); }
        if (!tid) vals[i] = red[0];
        __syncthreads();
    }
    if (!tid) {
        out[b*NLn + 0] = vals[0] + b2[0];
        out[b*NLn + 1] = vals[1] + b2[1];
        out[b*NLn + 2] = vals[2] + b2[2];
    }
}

extern "C" void kernel_launch(void* const* d_in, const int* in_sizes, int n_in,
                              void* d_out, int out_size) {
    const float* c_out  = (const float*)d_in[0];
    const float* e_emb  = (const float*)d_in[1];
    const int*   emask  = (const int*)  d_in[2];
    const float* W_c    = (const float*)d_in[3];
    const float* W_e    = (const float*)d_in[4];
    const float* v      = (const float*)d_in[5];
    const float* gate_w = (const float*)d_in[6];
    const float* gate_b = (const float*)d_in[7];
    const float* w1     = (const float*)d_in[8];
    const float* b1     = (const float*)d_in[9];
    const float* w2     = (const float*)d_in[10];
    const float* b2     = (const float*)d_in[11];
    float* out = (float*)d_out;

    cudaFuncSetAttribute(k_attn_mma, cudaFuncAttributeMaxDynamicSharedMemorySize, SMEM_TOTAL);

    k_cvtE<<<(Bn*Kn*Dn/4 + 255)/256, 256>>>(e_emb);
    k_cvtW<<<dim3(Dn/32, Dn/32, Hn), 256>>>(W_e);
    k_wcsum<<<(Hn*Dn*32 + 255)/256, 256>>>(W_c);
    k_attn_mma<<<dim3(NET, (Bn*Kn)/TCM, Hn), NTHREADS, SMEM_TOTAL>>>(c_out, v);
    k_softmax<<<Bn*Hn, Kn>>>(emask, out);
    k_eah<<<dim3(Dn/256, Bn), 256>>>(e_emb, out);
    k_gate<<<Bn, 256>>>(c_out, gate_w, gate_b, out);
    k_mlp1<<<dim3(Dn/N2, Bn/M2, 4), 256>>>(w1);
    k_logits<<<Bn, 128>>>(b1, w2, b2, out);
}